// round 3
// baseline (speedup 1.0000x reference)
#include <cuda_runtime.h>
#include <cstdint>
#include <cstddef>

// Problem constants (fixed by the reference)
#define D_DIM 256
#define NTOT  8192
#define BTOT  1024
#define KF    8

// Tiling
#define BM 64     // b rows per block
#define BN 32     // n cols per block
#define BK 16     // d-chunk
#define NJ 9      // mu + 8 v vectors per n
#define WROWS (BN*NJ)   // 288
#define WS 17           // padded row stride (floats) -> conflict-free scalar LDS

// Scratch (no cudaMalloc allowed)
__device__ float g_x2[BTOT];
__device__ float g_mu2[NTOT];
__device__ float g_muv[NTOT*KF];

// ---------------------------------------------------------------------------
// Precompute ||x_b||^2
__global__ void x2_kernel(const float* __restrict__ x) {
    __shared__ float red[256];
    int b = blockIdx.x, t = threadIdx.x;
    float v = x[b * D_DIM + t];
    red[t] = v * v;
    __syncthreads();
    for (int s = 128; s > 0; s >>= 1) {
        if (t < s) red[t] += red[t + s];
        __syncthreads();
    }
    if (t == 0) g_x2[b] = red[0];
}

// Precompute ||mu_n||^2 and mu_n . v_{n,k}
__global__ void mu_kernel(const float* __restrict__ mu, const float* __restrict__ v) {
    __shared__ float mus[256];
    __shared__ float red[256];
    int n = blockIdx.x, t = threadIdx.x;
    float m = mu[n * D_DIM + t];
    mus[t] = m;
    red[t] = m * m;
    __syncthreads();
    for (int s = 128; s > 0; s >>= 1) {
        if (t < s) red[t] += red[t + s];
        __syncthreads();
    }
    if (t == 0) g_mu2[n] = red[0];
    // warp w handles k = w
    int w = t >> 5, l = t & 31;
    const float* vk = v + ((size_t)n * KF + w) * D_DIM;
    float s = 0.f;
    #pragma unroll
    for (int i = 0; i < 8; i++) {
        int d = l + 32 * i;
        s = fmaf(mus[d], vk[d], s);
    }
    #pragma unroll
    for (int o = 16; o > 0; o >>= 1) s += __shfl_down_sync(0xffffffffu, s, o);
    if (l == 0) g_muv[n * KF + w] = s;
}

// ---------------------------------------------------------------------------
__device__ __forceinline__ void cp4(uint32_t dst, const float* src) {
    asm volatile("cp.async.ca.shared.global [%0], [%1], 4;\n" :: "r"(dst), "l"(src));
}
__device__ __forceinline__ void cp_commit() {
    asm volatile("cp.async.commit_group;\n" ::: "memory");
}
__device__ __forceinline__ void cp_wait1() {
    asm volatile("cp.async.wait_group 1;\n" ::: "memory");
}
__device__ __forceinline__ void cp_wait0() {
    asm volatile("cp.async.wait_group 0;\n" ::: "memory");
}

__global__ void __launch_bounds__(256)
hmu_main_kernel(const float* __restrict__ x,
                const float* __restrict__ mu,
                const float* __restrict__ lambda_base,
                const float* __restrict__ v,
                const float* __restrict__ omega,
                float* __restrict__ out) {
    // x_s: [kk][bm] so pairs of b are adjacent (8B f32x2 loads, warp-broadcast)
    __shared__ __align__(16) float x_s[2][BK][BM];       // 8 KB
    // w_s: row per (n_local*9 + j), stride 17 floats -> conflict-free
    __shared__ float w_s[2][WROWS][WS];                  // ~38.3 KB

    const int t  = threadIdx.x;
    const int tn = t & 31;       // n within tile (lane)
    const int tb = t >> 5;       // b-group (warp id) -> 8 b rows
    const int n0 = blockIdx.x * BN;
    const int b0 = blockIdx.y * BM;

    auto load_tiles = [&](int d0, int buf) {
        // x tile: 1024 floats, 4 per thread. Consecutive threads -> consecutive d.
        {
            int c = t;
            #pragma unroll
            for (int it = 0; it < (BM * BK) / 256; it++, c += 256) {
                int kk = c & (BK - 1);
                int bm = c >> 4;
                uint32_t dst = (uint32_t)__cvta_generic_to_shared(&x_s[buf][kk][bm]);
                cp4(dst, x + (size_t)(b0 + bm) * D_DIM + d0 + kk);
            }
        }
        // w tile: 288 rows x 16 floats. Row r = n_local*9 + j; j==0 -> mu, else v_{j-1}
        {
            int c = t;
            #pragma unroll
            for (int it = 0; it < (WROWS * BK) / 256; it++, c += 256) {
                int kk  = c & (BK - 1);
                int row = c >> 4;
                int nl  = row / NJ;
                int j   = row - nl * NJ;
                const float* src = (j == 0)
                    ? (mu + (size_t)(n0 + nl) * D_DIM + d0 + kk)
                    : (v + ((size_t)(n0 + nl) * KF + (j - 1)) * D_DIM + d0 + kk);
                uint32_t dst = (uint32_t)__cvta_generic_to_shared(&w_s[buf][row][kk]);
                cp4(dst, src);
            }
        }
    };

    // 9 dots x 4 f32x2 pairs (8 b rows) per thread
    unsigned long long acc[NJ][4];
    #pragma unroll
    for (int j = 0; j < NJ; j++)
        #pragma unroll
        for (int i = 0; i < 4; i++) acc[j][i] = 0ull;

    load_tiles(0, 0);
    cp_commit();

    const int NSTEP = D_DIM / BK;  // 16
    for (int s = 0; s < NSTEP; s++) {
        const int buf = s & 1;
        if (s + 1 < NSTEP) {
            load_tiles((s + 1) * BK, buf ^ 1);
            cp_commit();
            cp_wait1();            // step s's tile complete
        } else {
            cp_wait0();
        }
        __syncthreads();

        #pragma unroll
        for (int kk = 0; kk < BK; kk++) {
            unsigned long long xp[4];
            #pragma unroll
            for (int i = 0; i < 4; i++)
                xp[i] = *reinterpret_cast<const unsigned long long*>(
                            &x_s[buf][kk][tb * 8 + 2 * i]);
            #pragma unroll
            for (int j = 0; j < NJ; j++) {
                float wv = w_s[buf][tn * NJ + j][kk];
                unsigned long long wp;
                asm("mov.b64 %0, {%1, %1};" : "=l"(wp) : "f"(wv));
                #pragma unroll
                for (int i = 0; i < 4; i++)
                    asm("fma.rn.f32x2 %0, %1, %2, %0;"
                        : "+l"(acc[j][i]) : "l"(xp[i]), "l"(wp));
            }
        }
        __syncthreads();
    }

    // --------------------------- epilogue ---------------------------
    const int n = n0 + tn;
    const float lamn = lambda_base[n];
    const float mu2n = g_mu2[n];
    float om[KF], mv[KF];
    #pragma unroll
    for (int k = 0; k < KF; k++) {
        om[k] = omega[n * KF + k];
        mv[k] = g_muv[n * KF + k];
    }
    #pragma unroll
    for (int i = 0; i < 4; i++) {
        const int b = b0 + tb * 8 + 2 * i;
        float xm0, xm1;
        asm("mov.b64 {%0,%1}, %2;" : "=f"(xm0), "=f"(xm1) : "l"(acc[0][i]));
        float q0 = lamn * (g_x2[b]     - 2.f * xm0 + mu2n);
        float q1 = lamn * (g_x2[b + 1] - 2.f * xm1 + mu2n);
        #pragma unroll
        for (int k = 0; k < KF; k++) {
            float a0, a1;
            asm("mov.b64 {%0,%1}, %2;" : "=f"(a0), "=f"(a1) : "l"(acc[k + 1][i]));
            float p0 = a0 - mv[k];
            float p1 = a1 - mv[k];
            q0 = fmaf(om[k] * p0, p0, q0);
            q1 = fmaf(om[k] * p1, p1, q1);
        }
        out[(size_t)b * NTOT + n]       = __expf(q0 * (-1.0f / 256.0f));
        out[(size_t)(b + 1) * NTOT + n] = __expf(q1 * (-1.0f / 256.0f));
    }
}

// ---------------------------------------------------------------------------
extern "C" void kernel_launch(void* const* d_in, const int* in_sizes, int n_in,
                              void* d_out, int out_size) {
    // Inputs have pairwise-distinct sizes: select by element count (robust to order).
    const float *x = nullptr, *mu = nullptr, *lam = nullptr, *v = nullptr, *om = nullptr;
    for (int i = 0; i < n_in; i++) {
        switch (in_sizes[i]) {
            case BTOT * D_DIM:      x   = (const float*)d_in[i]; break;  // 262144
            case NTOT * D_DIM:      mu  = (const float*)d_in[i]; break;  // 2097152
            case NTOT:              lam = (const float*)d_in[i]; break;  // 8192
            case NTOT * KF * D_DIM: v   = (const float*)d_in[i]; break;  // 16777216
            case NTOT * KF:         om  = (const float*)d_in[i]; break;  // 65536
        }
    }

    x2_kernel<<<BTOT, 256>>>(x);
    mu_kernel<<<NTOT, 256>>>(mu, v);

    dim3 grid(NTOT / BN, BTOT / BM);   // (256, 16)
    hmu_main_kernel<<<grid, 256>>>(x, mu, lam, v, om, (float*)d_out);
}

// round 5
// speedup vs baseline: 1.5678x; 1.5678x over previous
#include <cuda_runtime.h>
#include <cuda_fp16.h>
#include <cstdint>
#include <cstddef>

// Problem constants
#define D_DIM 256
#define NTOT  8192
#define BTOT  1024
#define KF    8
#define NJROWS (NTOT*9)          // 73728 rows of W = [mu; v0..v7] per unit

// GEMM tiling
#define BM 128                   // b rows per CTA
#define BN 144                   // 16 units * 9
#define UNITS 16
#define KC 32                    // halves per chunk
#define NCHUNK 24                // K' = 3*256 = 768 -> 24 chunks
#define AST 40                   // smem row stride in halves (32 data + 8 pad) -> 80B

// Shared memory layout (bytes, dynamic)
#define A_BUF (BM*AST*2)         // 10240
#define B_BUF (BN*AST*2)         // 11520
#define A_OFF 0
#define B_OFF (2*A_BUF)          // 20480
// epilogue C tile overlaps GEMM buffers (used after GEMM completes)
#define C_STRIDE 145
#define PAR_OFF (BM*C_STRIDE*4)  // 74240
#define SMEM_TOTAL (PAR_OFF + 288*4)  // + lam[16] mu2[16] muv[128] om[128]

// Scratch (no cudaMalloc allowed) — hi/lo fp16 splits + Woodbury precomputes
__device__ __half g_xhi[BTOT*D_DIM];
__device__ __half g_xlo[BTOT*D_DIM];
__device__ __half g_whi[NJROWS*D_DIM];
__device__ __half g_wlo[NJROWS*D_DIM];
__device__ float  g_x2[BTOT];
__device__ float  g_mu2[NTOT];
__device__ float  g_muv[NTOT*KF];

// ---------------------------------------------------------------------------
__device__ __forceinline__ uint32_t smem_u32(const void* p) {
    uint32_t a;
    asm("{ .reg .u64 t; cvta.to.shared.u64 t, %1; cvt.u32.u64 %0, t; }"
        : "=r"(a) : "l"(p));
    return a;
}
__device__ __forceinline__ void cp16(uint32_t dst, const void* src) {
    asm volatile("cp.async.cg.shared.global [%0], [%1], 16;" :: "r"(dst), "l"(src));
}
__device__ __forceinline__ void cp_commit() {
    asm volatile("cp.async.commit_group;" ::: "memory");
}
__device__ __forceinline__ void cp_wait1() {
    asm volatile("cp.async.wait_group 1;" ::: "memory");
}
__device__ __forceinline__ void cp_wait0() {
    asm volatile("cp.async.wait_group 0;" ::: "memory");
}
__device__ __forceinline__ uint32_t lds32(uint32_t a) {
    uint32_t v;
    asm volatile("ld.shared.b32 %0, [%1];" : "=r"(v) : "r"(a));
    return v;
}
__device__ __forceinline__ void mma16816(float* c, const uint32_t* a, const uint32_t* b) {
    asm volatile(
        "mma.sync.aligned.m16n8k16.row.col.f32.f16.f16.f32 "
        "{%0,%1,%2,%3}, {%4,%5,%6,%7}, {%8,%9}, {%0,%1,%2,%3};"
        : "+f"(c[0]), "+f"(c[1]), "+f"(c[2]), "+f"(c[3])
        : "r"(a[0]), "r"(a[1]), "r"(a[2]), "r"(a[3]), "r"(b[0]), "r"(b[1]));
}

// ---------------------------------------------------------------------------
// Precompute: ||x||^2 and fp16 hi/lo split of x
__global__ void xconv_kernel(const float* __restrict__ x) {
    __shared__ float red[256];
    int b = blockIdx.x, t = threadIdx.x;
    float val = x[b * D_DIM + t];
    __half h = __float2half_rn(val);
    g_xhi[b * D_DIM + t] = h;
    g_xlo[b * D_DIM + t] = __float2half_rn(val - __half2float(h));
    red[t] = val * val;
    __syncthreads();
    for (int s = 128; s > 0; s >>= 1) {
        if (t < s) red[t] += red[t + s];
        __syncthreads();
    }
    if (t == 0) g_x2[b] = red[0];
}

// Precompute: ||mu||^2, mu.v_k, and hi/lo split of interleaved W rows
__global__ void wconv_kernel(const float* __restrict__ mu, const float* __restrict__ v) {
    __shared__ float mus[256];
    __shared__ float red[256];
    int n = blockIdx.x, t = threadIdx.x;
    float m = mu[(size_t)n * D_DIM + t];
    mus[t] = m;
    // mu row -> W row n*9
    {
        __half h = __float2half_rn(m);
        size_t o = (size_t)(n * 9) * D_DIM + t;
        g_whi[o] = h;
        g_wlo[o] = __float2half_rn(m - __half2float(h));
    }
    red[t] = m * m;
    __syncthreads();
    for (int s = 128; s > 0; s >>= 1) {
        if (t < s) red[t] += red[t + s];
        __syncthreads();
    }
    if (t == 0) g_mu2[n] = red[0];
    __syncthreads();
    #pragma unroll
    for (int k = 0; k < KF; k++) {
        float vv = v[((size_t)n * KF + k) * D_DIM + t];
        __half h = __float2half_rn(vv);
        size_t o = (size_t)(n * 9 + 1 + k) * D_DIM + t;
        g_whi[o] = h;
        g_wlo[o] = __float2half_rn(vv - __half2float(h));
        red[t] = m * vv;
        __syncthreads();
        for (int s = 128; s > 0; s >>= 1) {
            if (t < s) red[t] += red[t + s];
            __syncthreads();
        }
        if (t == 0) g_muv[n * KF + k] = red[0];
        __syncthreads();
    }
}

// ---------------------------------------------------------------------------
__global__ void __launch_bounds__(256, 1)
hmu_mma_kernel(const float* __restrict__ lambda_base,
               const float* __restrict__ omega,
               float* __restrict__ out) {
    extern __shared__ __align__(128) char smem[];
    const uint32_t sb = smem_u32(smem);
    float* Cs = (float*)smem;
    float* par = (float*)(smem + PAR_OFF);

    const int t    = threadIdx.x;
    const int wid  = t >> 5;
    const int lane = t & 31;
    const int wm   = wid & 3;      // 4 warps in M
    const int wn   = wid >> 2;     // 2 warps in N
    const int tg   = lane >> 2;    // 0..7
    const int tk   = lane & 3;     // 0..3
    const int bx   = blockIdx.x;   // 0..511 (n-blocks of 16 units)
    const int b0   = blockIdx.y * BM;
    const int n0u  = bx * UNITS;

    // Load epilogue params into smem (region disjoint from GEMM buffers)
    if (t < UNITS) {
        par[t]          = lambda_base[n0u + t];
        par[UNITS + t]  = g_mu2[n0u + t];
    }
    if (t < UNITS * KF) {
        par[32 + t]  = g_muv[n0u * KF + t];
        par[160 + t] = omega[n0u * KF + t];
    }

    // ---- GEMM over K' = 768 (thirds: AhiBhi | AhiBlo | AloBhi) ----
    auto load_chunk = [&](int s, int buf) {
        const int third = s >> 3;
        const int d0 = (s & 7) * KC;
        const __half* asrc = (third == 2) ? g_xlo : g_xhi;
        const __half* bsrc = (third == 1) ? g_wlo : g_whi;
        const uint32_t abase = sb + A_OFF + buf * A_BUF;
        const uint32_t bbase = sb + B_OFF + buf * B_BUF;
        // A: 128 rows x 32 halves = 512 x 16B
        #pragma unroll
        for (int i = 0; i < 2; i++) {
            int idx = t + 256 * i;
            int r = idx >> 2, c = idx & 3;
            cp16(abase + r * 80 + c * 16,
                 asrc + (size_t)(b0 + r) * D_DIM + d0 + c * 8);
        }
        // B: 144 rows x 32 halves = 576 x 16B
        #pragma unroll
        for (int i = 0; i < 2; i++) {
            int idx = t + 256 * i;
            int r = idx >> 2, c = idx & 3;
            cp16(bbase + r * 80 + c * 16,
                 bsrc + (size_t)(bx * BN + r) * D_DIM + d0 + c * 8);
        }
        if (t < 64) {
            int idx = 512 + t;
            int r = idx >> 2, c = idx & 3;
            cp16(bbase + r * 80 + c * 16,
                 bsrc + (size_t)(bx * BN + r) * D_DIM + d0 + c * 8);
        }
    };

    float acc[2][9][4];
    #pragma unroll
    for (int mi = 0; mi < 2; mi++)
        #pragma unroll
        for (int ni = 0; ni < 9; ni++)
            #pragma unroll
            for (int r = 0; r < 4; r++) acc[mi][ni][r] = 0.f;

    // per-thread frag base addresses (byte offsets into smem)
    const uint32_t a_tb = sb + A_OFF + (wm * 32 + tg) * 80 + tk * 4;
    const uint32_t b_tb = sb + B_OFF + (wn * 72 + tg) * 80 + tk * 4;

    load_chunk(0, 0);
    cp_commit();

    for (int s = 0; s < NCHUNK; s++) {
        const int buf = s & 1;
        if (s < NCHUNK - 1) {
            load_chunk(s + 1, buf ^ 1);
            cp_commit();
            cp_wait1();
        } else {
            cp_wait0();
        }
        __syncthreads();

        const uint32_t ab = a_tb + buf * A_BUF;
        const uint32_t bb = b_tb + buf * B_BUF;
        #pragma unroll
        for (int ks = 0; ks < 2; ks++) {
            const uint32_t kb = ks * 32;    // 16 halves = 32 bytes
            uint32_t a[2][4];
            #pragma unroll
            for (int mi = 0; mi < 2; mi++) {
                uint32_t base = ab + mi * 1280 + kb;   // 16 rows * 80B
                a[mi][0] = lds32(base);
                a[mi][1] = lds32(base + 640);          // row +8
                a[mi][2] = lds32(base + 16);           // k +8
                a[mi][3] = lds32(base + 656);
            }
            uint32_t b[9][2];
            #pragma unroll
            for (int ni = 0; ni < 9; ni++) {
                uint32_t base = bb + ni * 640 + kb;    // 8 rows * 80B
                b[ni][0] = lds32(base);
                b[ni][1] = lds32(base + 16);
            }
            #pragma unroll
            for (int mi = 0; mi < 2; mi++)
                #pragma unroll
                for (int ni = 0; ni < 9; ni++)
                    mma16816(acc[mi][ni], a[mi], b[ni]);
        }
        __syncthreads();
    }

    // ---- epilogue: accumulators -> smem C tile (regroup 9 cols per unit) ----
    #pragma unroll
    for (int mi = 0; mi < 2; mi++) {
        #pragma unroll
        for (int rh = 0; rh < 2; rh++) {
            int row = wm * 32 + mi * 16 + tg + rh * 8;
            #pragma unroll
            for (int ni = 0; ni < 9; ni++) {
                int col = wn * 72 + ni * 8 + tk * 2;
                Cs[row * C_STRIDE + col]     = acc[mi][ni][rh * 2];
                Cs[row * C_STRIDE + col + 1] = acc[mi][ni][rh * 2 + 1];
            }
        }
    }
    __syncthreads();

    #pragma unroll
    for (int i = 0; i < 8; i++) {
        int p = t + 256 * i;           // 0..2047 = 128 m x 16 u
        int m = p >> 4, u = p & 15;
        const float* c = Cs + m * C_STRIDE + u * 9;
        float xm = c[0];
        float q = par[u] * (g_x2[b0 + m] - 2.f * xm + par[UNITS + u]);
        #pragma unroll
        for (int k = 0; k < KF; k++) {
            float pv = c[1 + k] - par[32 + u * KF + k];
            q = fmaf(par[160 + u * KF + k] * pv, pv, q);
        }
        out[(size_t)(b0 + m) * NTOT + n0u + u] = __expf(q * (-1.0f / 256.0f));
    }
}

// ---------------------------------------------------------------------------
extern "C" void kernel_launch(void* const* d_in, const int* in_sizes, int n_in,
                              void* d_out, int out_size) {
    const float *x = nullptr, *mu = nullptr, *lam = nullptr, *v = nullptr, *om = nullptr;
    for (int i = 0; i < n_in; i++) {
        switch (in_sizes[i]) {
            case BTOT * D_DIM:      x   = (const float*)d_in[i]; break;
            case NTOT * D_DIM:      mu  = (const float*)d_in[i]; break;
            case NTOT:              lam = (const float*)d_in[i]; break;
            case NTOT * KF * D_DIM: v   = (const float*)d_in[i]; break;
            case NTOT * KF:         om  = (const float*)d_in[i]; break;
        }
    }

    xconv_kernel<<<BTOT, 256>>>(x);
    wconv_kernel<<<NTOT, 256>>>(mu, v);

    cudaFuncSetAttribute(hmu_mma_kernel,
                         cudaFuncAttributeMaxDynamicSharedMemorySize, SMEM_TOTAL);
    dim3 grid(NTOT / UNITS, BTOT / BM);   // (512, 8)
    hmu_mma_kernel<<<grid, 256, SMEM_TOTAL>>>(lam, om, (float*)d_out);
}

// round 6
// speedup vs baseline: 3.5231x; 2.2472x over previous
#include <cuda_runtime.h>
#include <cuda_fp16.h>
#include <cstdint>
#include <cstddef>

// Problem constants
#define D_DIM 256
#define NTOT  8192
#define BTOT  1024
#define KF    8

// GEMM tiling: C(1024 x 73728) = [xhi|xlo](1024 x 512) @ Whi^T, Whi reused for both halves
#define BM 128
#define BN 144                 // 16 units * 9 rows
#define UNITS 16
#define KC 32                  // halves per chunk
#define NCHUNK 8               // 8 * 32 = 256 = D

// SMEM stage: B(144x80B) + Ahi(128x80B) + Alo(128x80B)
#define STG   32000
#define B_O   0
#define AH_O  11520
#define AL_O  21760
#define C_STRIDE 145
#define PAR_OFF (BM*C_STRIDE*4)          // 74240
#define SMEM_TOTAL (PAR_OFF + 288*4)     // 75392

// Scratch (static __device__, no allocation)
__device__ __align__(16) __half g_xhi[BTOT*D_DIM];
__device__ __align__(16) __half g_xlo[BTOT*D_DIM];
__device__ __align__(16) __half g_whi[(size_t)NTOT*9*D_DIM];   // 37.75 MB
__device__ float g_x2[BTOT];
__device__ float g_mu2[NTOT];
__device__ float g_muv[NTOT*KF];

// ---------------------------------------------------------------------------
__device__ __forceinline__ uint32_t smem_u32(const void* p) {
    uint32_t a;
    asm("{ .reg .u64 t; cvta.to.shared.u64 t, %1; cvt.u32.u64 %0, t; }"
        : "=r"(a) : "l"(p));
    return a;
}
__device__ __forceinline__ void cp16(uint32_t dst, const void* src) {
    asm volatile("cp.async.cg.shared.global [%0], [%1], 16;" :: "r"(dst), "l"(src));
}
__device__ __forceinline__ void cp_commit() {
    asm volatile("cp.async.commit_group;" ::: "memory");
}
__device__ __forceinline__ void cp_wait1() {
    asm volatile("cp.async.wait_group 1;" ::: "memory");
}
__device__ __forceinline__ void cp_wait0() {
    asm volatile("cp.async.wait_group 0;" ::: "memory");
}
__device__ __forceinline__ void ldsm4(uint32_t* d, uint32_t a) {
    asm volatile("ldmatrix.sync.aligned.m8n8.x4.shared.b16 {%0,%1,%2,%3}, [%4];"
        : "=r"(d[0]), "=r"(d[1]), "=r"(d[2]), "=r"(d[3]) : "r"(a));
}
__device__ __forceinline__ void ldsm2(uint32_t* d, uint32_t a) {
    asm volatile("ldmatrix.sync.aligned.m8n8.x2.shared.b16 {%0,%1}, [%2];"
        : "=r"(d[0]), "=r"(d[1]) : "r"(a));
}
__device__ __forceinline__ void mma16816(float* c, const uint32_t* a, const uint32_t* b) {
    asm volatile(
        "mma.sync.aligned.m16n8k16.row.col.f32.f16.f16.f32 "
        "{%0,%1,%2,%3}, {%4,%5,%6,%7}, {%8,%9}, {%0,%1,%2,%3};"
        : "+f"(c[0]), "+f"(c[1]), "+f"(c[2]), "+f"(c[3])
        : "r"(a[0]), "r"(a[1]), "r"(a[2]), "r"(a[3]), "r"(b[0]), "r"(b[1]));
}

// ---------------------------------------------------------------------------
// x: hi/lo fp16 split + ||x||^2
__global__ void xconv_kernel(const float* __restrict__ x) {
    __shared__ float part[8];
    int b = blockIdx.x, t = threadIdx.x, w = t >> 5, l = t & 31;
    float val = x[b * D_DIM + t];
    __half h = __float2half_rn(val);
    g_xhi[b * D_DIM + t] = h;
    g_xlo[b * D_DIM + t] = __float2half_rn(val - __half2float(h));
    float s = val * val;
    #pragma unroll
    for (int o = 16; o > 0; o >>= 1) s += __shfl_down_sync(0xffffffffu, s, o);
    if (l == 0) part[w] = s;
    __syncthreads();
    if (t == 0) {
        float tot = 0.f;
        #pragma unroll
        for (int i = 0; i < 8; i++) tot += part[i];
        g_x2[b] = tot;
    }
}

// W = [mu; v0..v7] -> fp16; ||mu||^2; muv_k = mu . vhi_k (consistent quantization)
__global__ void wconv_kernel(const float* __restrict__ mu, const float* __restrict__ v) {
    __shared__ float mus[256];
    __shared__ float part[8];
    int n = blockIdx.x, t = threadIdx.x, w = t >> 5, l = t & 31;
    float m = mu[(size_t)n * D_DIM + t];
    mus[t] = m;
    g_whi[(size_t)(n * 9) * D_DIM + t] = __float2half_rn(m);
    float s = m * m;
    #pragma unroll
    for (int o = 16; o > 0; o >>= 1) s += __shfl_down_sync(0xffffffffu, s, o);
    if (l == 0) part[w] = s;
    __syncthreads();
    if (t == 0) {
        float tot = 0.f;
        #pragma unroll
        for (int i = 0; i < 8; i++) tot += part[i];
        g_mu2[n] = tot;
    }
    // warp w handles k = w: lane l covers d = l*8 .. l*8+7
    const float* vk = v + ((size_t)n * KF + w) * D_DIM + l * 8;
    float4 p0 = *(const float4*)(vk);
    float4 p1 = *(const float4*)(vk + 4);
    float fv[8] = {p0.x, p0.y, p0.z, p0.w, p1.x, p1.y, p1.z, p1.w};
    __half hh[8];
    float hv[8];
    #pragma unroll
    for (int i = 0; i < 8; i++) {
        hh[i] = __float2half_rn(fv[i]);
        hv[i] = __half2float(hh[i]);
    }
    uint4 pk;
    pk.x = (uint32_t)__half_as_ushort(hh[0]) | ((uint32_t)__half_as_ushort(hh[1]) << 16);
    pk.y = (uint32_t)__half_as_ushort(hh[2]) | ((uint32_t)__half_as_ushort(hh[3]) << 16);
    pk.z = (uint32_t)__half_as_ushort(hh[4]) | ((uint32_t)__half_as_ushort(hh[5]) << 16);
    pk.w = (uint32_t)__half_as_ushort(hh[6]) | ((uint32_t)__half_as_ushort(hh[7]) << 16);
    *(uint4*)(g_whi + (size_t)(n * 9 + 1 + w) * D_DIM + l * 8) = pk;
    float dot = 0.f;
    #pragma unroll
    for (int i = 0; i < 8; i++) dot = fmaf(mus[l * 8 + i], hv[i], dot);
    #pragma unroll
    for (int o = 16; o > 0; o >>= 1) dot += __shfl_down_sync(0xffffffffu, dot, o);
    if (l == 0) g_muv[n * KF + w] = dot;
}

// ---------------------------------------------------------------------------
__global__ void __launch_bounds__(256, 2)
hmu_mma_kernel(const float* __restrict__ lambda_base,
               const float* __restrict__ omega,
               float* __restrict__ out) {
    extern __shared__ __align__(128) char smem[];
    const uint32_t sb = smem_u32(smem);
    float* Cs  = (float*)smem;
    float* par = (float*)(smem + PAR_OFF);

    const int t    = threadIdx.x;
    const int wid  = t >> 5;
    const int lane = t & 31;
    const int wm   = wid & 3;       // 4 warps in M (32 rows each)
    const int wn   = wid >> 2;      // 2 warps in N (72 rows each)
    const int bx   = blockIdx.x;
    const int b0   = blockIdx.y * BM;
    const int n0u  = bx * UNITS;

    if (t < UNITS) {
        par[t]         = lambda_base[n0u + t];
        par[UNITS + t] = g_mu2[n0u + t];
    }
    if (t < UNITS * KF) {
        par[32 + t]  = g_muv[n0u * KF + t];
        par[160 + t] = omega[n0u * KF + t];
    }

    auto load_chunk = [&](int s, int buf) {
        const int d0 = s * KC;
        const uint32_t st = sb + buf * STG;
        #pragma unroll
        for (int i = 0; i < 2; i++) {
            int idx = t + 256 * i;
            int r = idx >> 2, c = idx & 3;
            cp16(st + B_O + r * 80 + c * 16,
                 g_whi + ((size_t)bx * BN + r) * D_DIM + d0 + c * 8);
        }
        if (t < 64) {
            int idx = 512 + t;
            int r = idx >> 2, c = idx & 3;
            cp16(st + B_O + r * 80 + c * 16,
                 g_whi + ((size_t)bx * BN + r) * D_DIM + d0 + c * 8);
        }
        #pragma unroll
        for (int i = 0; i < 2; i++) {
            int idx = t + 256 * i;
            int r = idx >> 2, c = idx & 3;
            cp16(st + AH_O + r * 80 + c * 16,
                 g_xhi + (size_t)(b0 + r) * D_DIM + d0 + c * 8);
            cp16(st + AL_O + r * 80 + c * 16,
                 g_xlo + (size_t)(b0 + r) * D_DIM + d0 + c * 8);
        }
    };

    float acc[2][9][4];
    #pragma unroll
    for (int mi = 0; mi < 2; mi++)
        #pragma unroll
        for (int ni = 0; ni < 9; ni++)
            #pragma unroll
            for (int r = 0; r < 4; r++) acc[mi][ni][r] = 0.f;

    // ldmatrix per-lane address components
    const int mq = lane >> 3, rr = lane & 7;
    const uint32_t a_off  = (uint32_t)((wm * 32 + (mq & 1) * 8 + rr) * 80 + (mq >> 1) * 16);
    const uint32_t b_off  = (uint32_t)((wn * 72 + (mq >> 1) * 8 + rr) * 80 + (mq & 1) * 16);
    const uint32_t b2_off = (uint32_t)((wn * 72 + 64 + rr) * 80 + ((lane >> 3) & 1) * 16);

    load_chunk(0, 0);
    cp_commit();

    for (int s = 0; s < NCHUNK; s++) {
        const int buf = s & 1;
        if (s < NCHUNK - 1) {
            load_chunk(s + 1, buf ^ 1);
            cp_commit();
            cp_wait1();
        } else {
            cp_wait0();
        }
        __syncthreads();

        const uint32_t st = sb + buf * STG;
        #pragma unroll
        for (int ks = 0; ks < 2; ks++) {
            const uint32_t kb = ks * 32;
            uint32_t ah[2][4], al[2][4];
            #pragma unroll
            for (int mi = 0; mi < 2; mi++) {
                ldsm4(ah[mi], st + AH_O + a_off + mi * (16 * 80) + kb);
                ldsm4(al[mi], st + AL_O + a_off + mi * (16 * 80) + kb);
            }
            #pragma unroll
            for (int n2 = 0; n2 < 4; n2++) {
                uint32_t bf[4];
                ldsm4(bf, st + B_O + b_off + n2 * (16 * 80) + kb);
                #pragma unroll
                for (int mi = 0; mi < 2; mi++) {
                    mma16816(acc[mi][2 * n2],     ah[mi], bf);
                    mma16816(acc[mi][2 * n2 + 1], ah[mi], bf + 2);
                    mma16816(acc[mi][2 * n2],     al[mi], bf);
                    mma16816(acc[mi][2 * n2 + 1], al[mi], bf + 2);
                }
            }
            {
                uint32_t bf[2];
                ldsm2(bf, st + B_O + b2_off + kb);
                #pragma unroll
                for (int mi = 0; mi < 2; mi++) {
                    mma16816(acc[mi][8], ah[mi], bf);
                    mma16816(acc[mi][8], al[mi], bf);
                }
            }
        }
        __syncthreads();
    }

    // ---- epilogue: regroup 9 columns per unit through smem ----
    const int tg = lane >> 2, tk = lane & 3;
    #pragma unroll
    for (int mi = 0; mi < 2; mi++) {
        #pragma unroll
        for (int rh = 0; rh < 2; rh++) {
            int row = wm * 32 + mi * 16 + tg + rh * 8;
            #pragma unroll
            for (int ni = 0; ni < 9; ni++) {
                int col = wn * 72 + ni * 8 + tk * 2;
                Cs[row * C_STRIDE + col]     = acc[mi][ni][rh * 2];
                Cs[row * C_STRIDE + col + 1] = acc[mi][ni][rh * 2 + 1];
            }
        }
    }
    __syncthreads();

    #pragma unroll
    for (int i = 0; i < 8; i++) {
        int p = t + 256 * i;            // 128 m x 16 u
        int m = p >> 4, u = p & 15;
        const float* c = Cs + m * C_STRIDE + u * 9;
        float xm = c[0];
        float q = par[u] * (g_x2[b0 + m] - 2.f * xm + par[UNITS + u]);
        #pragma unroll
        for (int k = 0; k < KF; k++) {
            float pv = c[1 + k] - par[32 + u * KF + k];
            q = fmaf(par[160 + u * KF + k] * pv, pv, q);
        }
        out[(size_t)(b0 + m) * NTOT + n0u + u] = __expf(q * (-1.0f / 256.0f));
    }
}

// ---------------------------------------------------------------------------
extern "C" void kernel_launch(void* const* d_in, const int* in_sizes, int n_in,
                              void* d_out, int out_size) {
    const float *x = nullptr, *mu = nullptr, *lam = nullptr, *v = nullptr, *om = nullptr;
    for (int i = 0; i < n_in; i++) {
        switch (in_sizes[i]) {
            case BTOT * D_DIM:      x   = (const float*)d_in[i]; break;
            case NTOT * D_DIM:      mu  = (const float*)d_in[i]; break;
            case NTOT:              lam = (const float*)d_in[i]; break;
            case NTOT * KF * D_DIM: v   = (const float*)d_in[i]; break;
            case NTOT * KF:         om  = (const float*)d_in[i]; break;
        }
    }

    xconv_kernel<<<BTOT, 256>>>(x);
    wconv_kernel<<<NTOT, 256>>>(mu, v);

    cudaFuncSetAttribute(hmu_mma_kernel,
                         cudaFuncAttributeMaxDynamicSharedMemorySize, SMEM_TOTAL);
    dim3 grid(NTOT / UNITS, BTOT / BM);   // (512, 8)
    hmu_mma_kernel<<<grid, 256, SMEM_TOTAL>>>(lam, om, (float*)d_out);
}

// round 7
// speedup vs baseline: 5.5175x; 1.5661x over previous
#include <cuda_runtime.h>
#include <cuda_fp16.h>
#include <cstdint>
#include <cstddef>

// Problem constants
#define D_DIM 256
#define NTOT  8192
#define BTOT  1024
#define KF    8

// GEMM: C(1024 x 73728) = xhi(1024 x 256) @ Whi^T   (single fp16 product)
#define BM 128
#define BN 144                 // 16 units * 9 rows
#define UNITS 16
#define KC 64                  // halves per chunk
#define NCHUNK 4               // 4 * 64 = 256 = D

// SMEM staging: rows hold 128B data + 16B pad (stride 144B, ldmatrix conflict-free)
#define RST 144
#define B_O 0
#define A_O (BN*RST)                      // 20736
#define STG (A_O + BM*RST)                // 39168
#define C_STRIDE 145
#define PAR_OFF (2*STG)                   // 78336
#define SMEM_TOTAL (PAR_OFF + 288*4)      // 79488

// Scratch (static __device__, no allocation)
__device__ __align__(16) __half g_xhi[BTOT*D_DIM];
__device__ __align__(16) __half g_whi[(size_t)NTOT*9*D_DIM];   // 37.75 MB
__device__ float g_x2[BTOT];
__device__ float g_mu2[NTOT];
__device__ float g_muv[NTOT*KF];

// ---------------------------------------------------------------------------
__device__ __forceinline__ uint32_t smem_u32(const void* p) {
    uint32_t a;
    asm("{ .reg .u64 t; cvta.to.shared.u64 t, %1; cvt.u32.u64 %0, t; }"
        : "=r"(a) : "l"(p));
    return a;
}
__device__ __forceinline__ void cp16(uint32_t dst, const void* src) {
    asm volatile("cp.async.cg.shared.global [%0], [%1], 16;" :: "r"(dst), "l"(src));
}
__device__ __forceinline__ void cp_commit() {
    asm volatile("cp.async.commit_group;" ::: "memory");
}
__device__ __forceinline__ void cp_wait1() {
    asm volatile("cp.async.wait_group 1;" ::: "memory");
}
__device__ __forceinline__ void cp_wait0() {
    asm volatile("cp.async.wait_group 0;" ::: "memory");
}
__device__ __forceinline__ void ldsm4(uint32_t* d, uint32_t a) {
    asm volatile("ldmatrix.sync.aligned.m8n8.x4.shared.b16 {%0,%1,%2,%3}, [%4];"
        : "=r"(d[0]), "=r"(d[1]), "=r"(d[2]), "=r"(d[3]) : "r"(a));
}
__device__ __forceinline__ void ldsm2(uint32_t* d, uint32_t a) {
    asm volatile("ldmatrix.sync.aligned.m8n8.x2.shared.b16 {%0,%1}, [%2];"
        : "=r"(d[0]), "=r"(d[1]) : "r"(a));
}
__device__ __forceinline__ void mma16816(float* c, const uint32_t* a, const uint32_t* b) {
    asm volatile(
        "mma.sync.aligned.m16n8k16.row.col.f32.f16.f16.f32 "
        "{%0,%1,%2,%3}, {%4,%5,%6,%7}, {%8,%9}, {%0,%1,%2,%3};"
        : "+f"(c[0]), "+f"(c[1]), "+f"(c[2]), "+f"(c[3])
        : "r"(a[0]), "r"(a[1]), "r"(a[2]), "r"(a[3]), "r"(b[0]), "r"(b[1]));
}

// ---------------------------------------------------------------------------
// x -> fp16, ||x||^2
__global__ void xconv_kernel(const float* __restrict__ x) {
    __shared__ float part[8];
    int b = blockIdx.x, t = threadIdx.x, w = t >> 5, l = t & 31;
    float val = x[b * D_DIM + t];
    g_xhi[b * D_DIM + t] = __float2half_rn(val);
    float s = val * val;
    #pragma unroll
    for (int o = 16; o > 0; o >>= 1) s += __shfl_down_sync(0xffffffffu, s, o);
    if (l == 0) part[w] = s;
    __syncthreads();
    if (t == 0) {
        float tot = 0.f;
        #pragma unroll
        for (int i = 0; i < 8; i++) tot += part[i];
        g_x2[b] = tot;
    }
}

// W = [mu; v0..v7] -> fp16; ||mu||^2; muv_k = mu . vhi_k (consistent quantization)
__global__ void wconv_kernel(const float* __restrict__ mu, const float* __restrict__ v) {
    __shared__ float mus[256];
    __shared__ float part[8];
    int n = blockIdx.x, t = threadIdx.x, w = t >> 5, l = t & 31;
    float m = mu[(size_t)n * D_DIM + t];
    mus[t] = m;
    g_whi[(size_t)(n * 9) * D_DIM + t] = __float2half_rn(m);
    float s = m * m;
    #pragma unroll
    for (int o = 16; o > 0; o >>= 1) s += __shfl_down_sync(0xffffffffu, s, o);
    if (l == 0) part[w] = s;
    __syncthreads();
    if (t == 0) {
        float tot = 0.f;
        #pragma unroll
        for (int i = 0; i < 8; i++) tot += part[i];
        g_mu2[n] = tot;
    }
    const float* vk = v + ((size_t)n * KF + w) * D_DIM + l * 8;
    float4 p0 = *(const float4*)(vk);
    float4 p1 = *(const float4*)(vk + 4);
    float fv[8] = {p0.x, p0.y, p0.z, p0.w, p1.x, p1.y, p1.z, p1.w};
    __half hh[8];
    float hv[8];
    #pragma unroll
    for (int i = 0; i < 8; i++) {
        hh[i] = __float2half_rn(fv[i]);
        hv[i] = __half2float(hh[i]);
    }
    uint4 pk;
    pk.x = (uint32_t)__half_as_ushort(hh[0]) | ((uint32_t)__half_as_ushort(hh[1]) << 16);
    pk.y = (uint32_t)__half_as_ushort(hh[2]) | ((uint32_t)__half_as_ushort(hh[3]) << 16);
    pk.z = (uint32_t)__half_as_ushort(hh[4]) | ((uint32_t)__half_as_ushort(hh[5]) << 16);
    pk.w = (uint32_t)__half_as_ushort(hh[6]) | ((uint32_t)__half_as_ushort(hh[7]) << 16);
    *(uint4*)(g_whi + (size_t)(n * 9 + 1 + w) * D_DIM + l * 8) = pk;
    float dot = 0.f;
    #pragma unroll
    for (int i = 0; i < 8; i++) dot = fmaf(mus[l * 8 + i], hv[i], dot);
    #pragma unroll
    for (int o = 16; o > 0; o >>= 1) dot += __shfl_down_sync(0xffffffffu, dot, o);
    if (l == 0) g_muv[n * KF + w] = dot;
}

// ---------------------------------------------------------------------------
__global__ void __launch_bounds__(256, 2)
hmu_mma_kernel(const float* __restrict__ lambda_base,
               const float* __restrict__ omega,
               float* __restrict__ out) {
    extern __shared__ __align__(128) char smem[];
    const uint32_t sb = smem_u32(smem);
    float* Cs  = (float*)smem;
    float* par = (float*)(smem + PAR_OFF);

    const int t    = threadIdx.x;
    const int wid  = t >> 5;
    const int lane = t & 31;
    const int wm   = wid & 3;       // 4 warps in M (32 rows each)
    const int wn   = wid >> 2;      // 2 warps in N (72 rows each)
    const int bx   = blockIdx.x;
    const int b0   = blockIdx.y * BM;
    const int n0u  = bx * UNITS;

    if (t < UNITS) {
        par[t]         = lambda_base[n0u + t];
        par[UNITS + t] = g_mu2[n0u + t];
    }
    if (t < UNITS * KF) {
        par[32 + t]  = g_muv[n0u * KF + t];
        par[160 + t] = omega[n0u * KF + t];
    }

    auto load_chunk = [&](int s, int buf) {
        const int d0 = s * KC;
        const uint32_t st = sb + buf * STG;
        // B: 144 rows x 128B = 1152 x 16B segments
        #pragma unroll
        for (int i = 0; i < 4; i++) {
            int idx = t + 256 * i;
            int r = idx >> 3, c = idx & 7;
            cp16(st + B_O + r * RST + c * 16,
                 g_whi + ((size_t)bx * BN + r) * D_DIM + d0 + c * 8);
        }
        if (t < 128) {
            int idx = 1024 + t;
            int r = idx >> 3, c = idx & 7;
            cp16(st + B_O + r * RST + c * 16,
                 g_whi + ((size_t)bx * BN + r) * D_DIM + d0 + c * 8);
        }
        // A: 128 rows x 128B = 1024 x 16B segments
        #pragma unroll
        for (int i = 0; i < 4; i++) {
            int idx = t + 256 * i;
            int r = idx >> 3, c = idx & 7;
            cp16(st + A_O + r * RST + c * 16,
                 g_xhi + (size_t)(b0 + r) * D_DIM + d0 + c * 8);
        }
    };

    float acc[2][9][4];
    #pragma unroll
    for (int mi = 0; mi < 2; mi++)
        #pragma unroll
        for (int ni = 0; ni < 9; ni++)
            #pragma unroll
            for (int r = 0; r < 4; r++) acc[mi][ni][r] = 0.f;

    // ldmatrix per-lane addresses
    const int mq = lane >> 3, rr = lane & 7;
    const uint32_t a_off  = (uint32_t)((wm * 32 + (mq & 1) * 8 + rr) * RST + (mq >> 1) * 16);
    const uint32_t b_off  = (uint32_t)((wn * 72 + (mq >> 1) * 8 + rr) * RST + (mq & 1) * 16);
    const uint32_t b2_off = (uint32_t)((wn * 72 + 64 + rr) * RST + ((lane >> 3) & 1) * 16);

    load_chunk(0, 0);
    cp_commit();

    for (int s = 0; s < NCHUNK; s++) {
        const int buf = s & 1;
        if (s < NCHUNK - 1) {
            load_chunk(s + 1, buf ^ 1);
            cp_commit();
            cp_wait1();
        } else {
            cp_wait0();
        }
        __syncthreads();

        const uint32_t st = sb + buf * STG;
        #pragma unroll
        for (int ks = 0; ks < 4; ks++) {          // 4 x k16 per 64-half chunk
            const uint32_t kb = ks * 32;
            uint32_t ah[2][4];
            #pragma unroll
            for (int mi = 0; mi < 2; mi++)
                ldsm4(ah[mi], st + A_O + a_off + mi * (16 * RST) + kb);
            #pragma unroll
            for (int n2 = 0; n2 < 4; n2++) {
                uint32_t bf[4];
                ldsm4(bf, st + B_O + b_off + n2 * (16 * RST) + kb);
                #pragma unroll
                for (int mi = 0; mi < 2; mi++) {
                    mma16816(acc[mi][2 * n2],     ah[mi], bf);
                    mma16816(acc[mi][2 * n2 + 1], ah[mi], bf + 2);
                }
            }
            {
                uint32_t bf[2];
                ldsm2(bf, st + B_O + b2_off + kb);
                #pragma unroll
                for (int mi = 0; mi < 2; mi++)
                    mma16816(acc[mi][8], ah[mi], bf);
            }
        }
        __syncthreads();
    }

    // ---- epilogue: regroup 9 columns per unit through smem ----
    const int tg = lane >> 2, tk = lane & 3;
    #pragma unroll
    for (int mi = 0; mi < 2; mi++) {
        #pragma unroll
        for (int rh = 0; rh < 2; rh++) {
            int row = wm * 32 + mi * 16 + tg + rh * 8;
            #pragma unroll
            for (int ni = 0; ni < 9; ni++) {
                int col = wn * 72 + ni * 8 + tk * 2;
                Cs[row * C_STRIDE + col]     = acc[mi][ni][rh * 2];
                Cs[row * C_STRIDE + col + 1] = acc[mi][ni][rh * 2 + 1];
            }
        }
    }
    __syncthreads();

    #pragma unroll
    for (int i = 0; i < 8; i++) {
        int p = t + 256 * i;            // 128 m x 16 u
        int m = p >> 4, u = p & 15;
        const float* c = Cs + m * C_STRIDE + u * 9;
        float xm = c[0];
        float q = par[u] * (g_x2[b0 + m] - 2.f * xm + par[UNITS + u]);
        #pragma unroll
        for (int k = 0; k < KF; k++) {
            float pv = c[1 + k] - par[32 + u * KF + k];
            q = fmaf(par[160 + u * KF + k] * pv, pv, q);
        }
        out[(size_t)(b0 + m) * NTOT + n0u + u] = __expf(q * (-1.0f / 256.0f));
    }
}

// ---------------------------------------------------------------------------
extern "C" void kernel_launch(void* const* d_in, const int* in_sizes, int n_in,
                              void* d_out, int out_size) {
    const float *x = nullptr, *mu = nullptr, *lam = nullptr, *v = nullptr, *om = nullptr;
    for (int i = 0; i < n_in; i++) {
        switch (in_sizes[i]) {
            case BTOT * D_DIM:      x   = (const float*)d_in[i]; break;
            case NTOT * D_DIM:      mu  = (const float*)d_in[i]; break;
            case NTOT:              lam = (const float*)d_in[i]; break;
            case NTOT * KF * D_DIM: v   = (const float*)d_in[i]; break;
            case NTOT * KF:         om  = (const float*)d_in[i]; break;
        }
    }

    xconv_kernel<<<BTOT, 256>>>(x);
    wconv_kernel<<<NTOT, 256>>>(mu, v);

    cudaFuncSetAttribute(hmu_mma_kernel,
                         cudaFuncAttributeMaxDynamicSharedMemorySize, SMEM_TOTAL);
    dim3 grid(NTOT / UNITS, BTOT / BM);   // (512, 8)
    hmu_mma_kernel<<<grid, 256, SMEM_TOTAL>>>(lam, om, (float*)d_out);
}

// round 8
// speedup vs baseline: 5.5749x; 1.0104x over previous
#include <cuda_runtime.h>
#include <cuda_fp16.h>
#include <cstdint>
#include <cstddef>

// Problem constants
#define D_DIM 256
#define NTOT  8192
#define BTOT  1024
#define KF    8

// GEMM: C(1024 x 73728) = xhi(1024 x 256) @ Whi^T  (single fp16 product)
#define BM 128
#define BN 144                  // 16 units * 9 rows
#define UNITS 16
#define KC 64                   // halves per chunk (128 bytes)
#define NCHUNK 4                // 4 * 64 = 256 = D

// SMEM: 3-stage, swizzled 128B rows (no pad)
#define B_O 0
#define A_O (BN*128)                      // 18432
#define STG (A_O + BM*128)                // 34816 (multiple of 1024)
#define NSTAGE 3
#define C_STRIDE 145
#define PAR_OFF (NSTAGE*STG)              // 104448
#define SMEM_TOTAL (PAR_OFF + 288*4)      // 105600

#define SWC(col, xr) ((uint32_t)(col) ^ (uint32_t)(xr))

// Scratch (static __device__, no allocation)
__device__ __align__(16) __half g_xhi[BTOT*D_DIM];
__device__ __align__(16) __half g_whi[(size_t)NTOT*9*D_DIM];   // 37.75 MB
__device__ float g_x2[BTOT];
__device__ float g_mu2[NTOT];
__device__ float g_muv[NTOT*KF];

// ---------------------------------------------------------------------------
__device__ __forceinline__ uint32_t smem_u32(const void* p) {
    uint32_t a;
    asm("{ .reg .u64 t; cvta.to.shared.u64 t, %1; cvt.u32.u64 %0, t; }"
        : "=r"(a) : "l"(p));
    return a;
}
__device__ __forceinline__ void cp16(uint32_t dst, const void* src) {
    asm volatile("cp.async.cg.shared.global [%0], [%1], 16;" :: "r"(dst), "l"(src));
}
__device__ __forceinline__ void cp_commit() {
    asm volatile("cp.async.commit_group;" ::: "memory");
}
__device__ __forceinline__ void cp_wait1() {
    asm volatile("cp.async.wait_group 1;" ::: "memory");
}
__device__ __forceinline__ void cp_wait0() {
    asm volatile("cp.async.wait_group 0;" ::: "memory");
}
__device__ __forceinline__ void ldsm4(uint32_t* d, uint32_t a) {
    asm volatile("ldmatrix.sync.aligned.m8n8.x4.shared.b16 {%0,%1,%2,%3}, [%4];"
        : "=r"(d[0]), "=r"(d[1]), "=r"(d[2]), "=r"(d[3]) : "r"(a));
}
__device__ __forceinline__ void ldsm2(uint32_t* d, uint32_t a) {
    asm volatile("ldmatrix.sync.aligned.m8n8.x2.shared.b16 {%0,%1}, [%2];"
        : "=r"(d[0]), "=r"(d[1]) : "r"(a));
}
__device__ __forceinline__ void mma16816(float* c, const uint32_t* a, const uint32_t* b) {
    asm volatile(
        "mma.sync.aligned.m16n8k16.row.col.f32.f16.f16.f32 "
        "{%0,%1,%2,%3}, {%4,%5,%6,%7}, {%8,%9}, {%0,%1,%2,%3};"
        : "+f"(c[0]), "+f"(c[1]), "+f"(c[2]), "+f"(c[3])
        : "r"(a[0]), "r"(a[1]), "r"(a[2]), "r"(a[3]), "r"(b[0]), "r"(b[1]));
}

// ---------------------------------------------------------------------------
// Fused precompute: blocks [0,1024) -> x path; [1024,9216) -> W path
__global__ void precomp_kernel(const float* __restrict__ x,
                               const float* __restrict__ mu,
                               const float* __restrict__ v) {
    __shared__ float mus[256];
    __shared__ float part[8];
    const int t = threadIdx.x, w = t >> 5, l = t & 31;

    if (blockIdx.x < BTOT) {
        int b = blockIdx.x;
        float val = x[b * D_DIM + t];
        g_xhi[b * D_DIM + t] = __float2half_rn(val);
        float s = val * val;
        #pragma unroll
        for (int o = 16; o > 0; o >>= 1) s += __shfl_down_sync(0xffffffffu, s, o);
        if (l == 0) part[w] = s;
        __syncthreads();
        if (t == 0) {
            float tot = 0.f;
            #pragma unroll
            for (int i = 0; i < 8; i++) tot += part[i];
            g_x2[b] = tot;
        }
        return;
    }

    int n = blockIdx.x - BTOT;
    float m = mu[(size_t)n * D_DIM + t];
    mus[t] = m;
    g_whi[(size_t)(n * 9) * D_DIM + t] = __float2half_rn(m);
    float s = m * m;
    #pragma unroll
    for (int o = 16; o > 0; o >>= 1) s += __shfl_down_sync(0xffffffffu, s, o);
    if (l == 0) part[w] = s;
    __syncthreads();
    if (t == 0) {
        float tot = 0.f;
        #pragma unroll
        for (int i = 0; i < 8; i++) tot += part[i];
        g_mu2[n] = tot;
    }
    // warp w handles k = w; lane l covers d = l*8..l*8+7
    const float* vk = v + ((size_t)n * KF + w) * D_DIM + l * 8;
    float4 p0 = *(const float4*)(vk);
    float4 p1 = *(const float4*)(vk + 4);
    float fv[8] = {p0.x, p0.y, p0.z, p0.w, p1.x, p1.y, p1.z, p1.w};
    __half hh[8];
    float hv[8];
    #pragma unroll
    for (int i = 0; i < 8; i++) {
        hh[i] = __float2half_rn(fv[i]);
        hv[i] = __half2float(hh[i]);
    }
    uint4 pk;
    pk.x = (uint32_t)__half_as_ushort(hh[0]) | ((uint32_t)__half_as_ushort(hh[1]) << 16);
    pk.y = (uint32_t)__half_as_ushort(hh[2]) | ((uint32_t)__half_as_ushort(hh[3]) << 16);
    pk.z = (uint32_t)__half_as_ushort(hh[4]) | ((uint32_t)__half_as_ushort(hh[5]) << 16);
    pk.w = (uint32_t)__half_as_ushort(hh[6]) | ((uint32_t)__half_as_ushort(hh[7]) << 16);
    *(uint4*)(g_whi + (size_t)(n * 9 + 1 + w) * D_DIM + l * 8) = pk;
    float dot = 0.f;
    #pragma unroll
    for (int i = 0; i < 8; i++) dot = fmaf(mus[l * 8 + i], hv[i], dot);
    #pragma unroll
    for (int o = 16; o > 0; o >>= 1) dot += __shfl_down_sync(0xffffffffu, dot, o);
    if (l == 0) g_muv[n * KF + w] = dot;
}

// ---------------------------------------------------------------------------
__global__ void __launch_bounds__(256, 2)
hmu_mma_kernel(const float* __restrict__ lambda_base,
               const float* __restrict__ omega,
               float* __restrict__ out) {
    extern __shared__ __align__(1024) char smem[];
    const uint32_t sb = smem_u32(smem);
    float* Cs  = (float*)smem;
    float* par = (float*)(smem + PAR_OFF);

    const int t    = threadIdx.x;
    const int wid  = t >> 5;
    const int lane = t & 31;
    const int wm   = wid & 3;       // 4 warps in M
    const int wn   = wid >> 2;      // 2 warps in N
    const int bx   = blockIdx.x;
    const int b0   = blockIdx.y * BM;
    const int n0u  = bx * UNITS;

    // cp.async staging: thread covers (row r, 16B seg c), swizzled
    auto load_chunk = [&](int s, int buf) {
        const int d0 = s * KC;
        const uint32_t st = sb + buf * STG;
        #pragma unroll
        for (int i = 0; i < 4; i++) {
            int idx = t + 256 * i;
            int r = idx >> 3, c = idx & 7;
            cp16(st + B_O + r * 128 + SWC(c * 16, (r & 7) * 16),
                 g_whi + ((size_t)bx * BN + r) * D_DIM + d0 + c * 8);
        }
        if (t < 128) {
            int idx = 1024 + t;
            int r = idx >> 3, c = idx & 7;
            cp16(st + B_O + r * 128 + SWC(c * 16, (r & 7) * 16),
                 g_whi + ((size_t)bx * BN + r) * D_DIM + d0 + c * 8);
        }
        #pragma unroll
        for (int i = 0; i < 4; i++) {
            int idx = t + 256 * i;
            int r = idx >> 3, c = idx & 7;
            cp16(st + A_O + r * 128 + SWC(c * 16, (r & 7) * 16),
                 g_xhi + (size_t)(b0 + r) * D_DIM + d0 + c * 8);
        }
    };

    // Prologue: 2 chunks in flight before first compute
    load_chunk(0, 0);
    cp_commit();
    load_chunk(1, 1);
    cp_commit();

    if (t < UNITS) {
        par[t]         = lambda_base[n0u + t];
        par[UNITS + t] = g_mu2[n0u + t];
    }
    if (t < UNITS * KF) {
        par[32 + t]  = g_muv[n0u * KF + t];
        par[160 + t] = omega[n0u * KF + t];
    }

    float acc[2][9][4];
    #pragma unroll
    for (int mi = 0; mi < 2; mi++)
        #pragma unroll
        for (int ni = 0; ni < 9; ni++)
            #pragma unroll
            for (int r = 0; r < 4; r++) acc[mi][ni][r] = 0.f;

    // ldmatrix per-lane address components (row, col-base, swizzle xor)
    const int mq = lane >> 3, rr = lane & 7;
    const uint32_t rowA  = (uint32_t)(wm * 32 + (mq & 1) * 8 + rr);
    const uint32_t colA  = (uint32_t)((mq >> 1) * 16);
    const uint32_t xorA  = (rowA & 7) * 16;
    const uint32_t rowB  = (uint32_t)(wn * 72 + (mq >> 1) * 8 + rr);
    const uint32_t colB  = (uint32_t)((mq & 1) * 16);
    const uint32_t xorB  = (rowB & 7) * 16;
    const uint32_t rowB2 = (uint32_t)(wn * 72 + 64 + rr);
    const uint32_t colB2 = (uint32_t)(((lane >> 3) & 1) * 16);
    const uint32_t xorB2 = (rowB2 & 7) * 16;

    for (int s = 0; s < NCHUNK; s++) {
        if (s < NCHUNK - 1) cp_wait1(); else cp_wait0();
        __syncthreads();
        if (s < NCHUNK - 2) {
            load_chunk(s + 2, (s + 2) % NSTAGE);
            cp_commit();
        }

        const uint32_t st = sb + (s % NSTAGE) * STG;
        const uint32_t aB = st + A_O + rowA * 128;
        const uint32_t bB = st + B_O + rowB * 128;
        const uint32_t b2B = st + B_O + rowB2 * 128;
        #pragma unroll
        for (int ks = 0; ks < 4; ks++) {       // 4 x k16 per 64-half chunk
            const uint32_t kb = ks * 32;
            uint32_t ah[2][4];
            #pragma unroll
            for (int mi = 0; mi < 2; mi++)
                ldsm4(ah[mi], aB + mi * (16 * 128) + SWC(colA + kb, xorA));
            #pragma unroll
            for (int n2 = 0; n2 < 4; n2++) {
                uint32_t bf[4];
                ldsm4(bf, bB + n2 * (16 * 128) + SWC(colB + kb, xorB));
                #pragma unroll
                for (int mi = 0; mi < 2; mi++) {
                    mma16816(acc[mi][2 * n2],     ah[mi], bf);
                    mma16816(acc[mi][2 * n2 + 1], ah[mi], bf + 2);
                }
            }
            {
                uint32_t bf[2];
                ldsm2(bf, b2B + SWC(colB2 + kb, xorB2));
                #pragma unroll
                for (int mi = 0; mi < 2; mi++)
                    mma16816(acc[mi][8], ah[mi], bf);
            }
        }
    }
    __syncthreads();   // all reads of stage buffers done before C-tile overwrite

    // ---- epilogue: regroup 9 columns per unit through smem ----
    const int tg = lane >> 2, tk = lane & 3;
    #pragma unroll
    for (int mi = 0; mi < 2; mi++) {
        #pragma unroll
        for (int rh = 0; rh < 2; rh++) {
            int row = wm * 32 + mi * 16 + tg + rh * 8;
            #pragma unroll
            for (int ni = 0; ni < 9; ni++) {
                int col = wn * 72 + ni * 8 + tk * 2;
                Cs[row * C_STRIDE + col]     = acc[mi][ni][rh * 2];
                Cs[row * C_STRIDE + col + 1] = acc[mi][ni][rh * 2 + 1];
            }
        }
    }
    __syncthreads();

    #pragma unroll
    for (int i = 0; i < 8; i++) {
        int p = t + 256 * i;            // 128 m x 16 u
        int m = p >> 4, u = p & 15;
        const float* c = Cs + m * C_STRIDE + u * 9;
        float xm = c[0];
        float q = par[u] * (g_x2[b0 + m] - 2.f * xm + par[UNITS + u]);
        #pragma unroll
        for (int k = 0; k < KF; k++) {
            float pv = c[1 + k] - par[32 + u * KF + k];
            q = fmaf(par[160 + u * KF + k] * pv, pv, q);
        }
        out[(size_t)(b0 + m) * NTOT + n0u + u] = __expf(q * (-1.0f / 256.0f));
    }
}

// ---------------------------------------------------------------------------
extern "C" void kernel_launch(void* const* d_in, const int* in_sizes, int n_in,
                              void* d_out, int out_size) {
    const float *x = nullptr, *mu = nullptr, *lam = nullptr, *v = nullptr, *om = nullptr;
    for (int i = 0; i < n_in; i++) {
        switch (in_sizes[i]) {
            case BTOT * D_DIM:      x   = (const float*)d_in[i]; break;
            case NTOT * D_DIM:      mu  = (const float*)d_in[i]; break;
            case NTOT:              lam = (const float*)d_in[i]; break;
            case NTOT * KF * D_DIM: v   = (const float*)d_in[i]; break;
            case NTOT * KF:         om  = (const float*)d_in[i]; break;
        }
    }

    precomp_kernel<<<BTOT + NTOT, 256>>>(x, mu, v);

    cudaFuncSetAttribute(hmu_mma_kernel,
                         cudaFuncAttributeMaxDynamicSharedMemorySize, SMEM_TOTAL);
    dim3 grid(NTOT / UNITS, BTOT / BM);   // (512, 8)
    hmu_mma_kernel<<<grid, 256, SMEM_TOTAL>>>(lam, om, (float*)d_out);
}

// round 10
// speedup vs baseline: 5.9048x; 1.0592x over previous
#include <cuda_runtime.h>
#include <cuda_fp16.h>
#include <cstdint>
#include <cstddef>

// Problem constants
#define D_DIM 256
#define NTOT  8192
#define BTOT  1024
#define KF    8

// GEMM: C(1024 x 73728) = xhi(1024 x 256) @ Whi^T  (single fp16 product)
// CTA tile 128x144, 128 threads (4 warps: 2 in M x 2 in N), warp tile 64x72.
#define BM 128
#define BN 144                  // 16 units * 9 rows
#define UNITS 16
#define KC 64                   // halves per chunk (128 bytes)
#define NCHUNK 4                // 4 * 64 = 256 = D
#define NTHREADS 128

// SMEM: 3-stage, swizzled 128B rows (no pad)
#define B_O 0
#define A_O (BN*128)                      // 18432
#define STG (A_O + BM*128)                // 34816
#define NSTAGE 3
#define C_STRIDE 145
#define PAR_OFF (NSTAGE*STG)              // 104448
#define SMEM_TOTAL (PAR_OFF + 288*4)      // 105600

#define SWC(col, xr) ((uint32_t)(col) ^ (uint32_t)(xr))

// Scratch (static __device__, no allocation)
__device__ __align__(16) __half g_xhi[BTOT*D_DIM];
__device__ __align__(16) __half g_whi[(size_t)NTOT*9*D_DIM];   // 37.75 MB
__device__ float g_x2[BTOT];
__device__ float g_mu2[NTOT];
__device__ float g_muv[NTOT*KF];

// ---------------------------------------------------------------------------
__device__ __forceinline__ uint32_t smem_u32(const void* p) {
    uint32_t a;
    asm("{ .reg .u64 t; cvta.to.shared.u64 t, %1; cvt.u32.u64 %0, t; }"
        : "=r"(a) : "l"(p));
    return a;
}
__device__ __forceinline__ void cp16(uint32_t dst, const void* src) {
    asm volatile("cp.async.cg.shared.global [%0], [%1], 16;" :: "r"(dst), "l"(src));
}
__device__ __forceinline__ void cp_commit() {
    asm volatile("cp.async.commit_group;" ::: "memory");
}
__device__ __forceinline__ void cp_wait1() {
    asm volatile("cp.async.wait_group 1;" ::: "memory");
}
__device__ __forceinline__ void cp_wait0() {
    asm volatile("cp.async.wait_group 0;" ::: "memory");
}
__device__ __forceinline__ void ldsm4(uint32_t* d, uint32_t a) {
    asm volatile("ldmatrix.sync.aligned.m8n8.x4.shared.b16 {%0,%1,%2,%3}, [%4];"
        : "=r"(d[0]), "=r"(d[1]), "=r"(d[2]), "=r"(d[3]) : "r"(a));
}
__device__ __forceinline__ void ldsm2(uint32_t* d, uint32_t a) {
    asm volatile("ldmatrix.sync.aligned.m8n8.x2.shared.b16 {%0,%1}, [%2];"
        : "=r"(d[0]), "=r"(d[1]) : "r"(a));
}
__device__ __forceinline__ void mma16816(float* c, const uint32_t* a, const uint32_t* b) {
    asm volatile(
        "mma.sync.aligned.m16n8k16.row.col.f32.f16.f16.f32 "
        "{%0,%1,%2,%3}, {%4,%5,%6,%7}, {%8,%9}, {%0,%1,%2,%3};"
        : "+f"(c[0]), "+f"(c[1]), "+f"(c[2]), "+f"(c[3])
        : "r"(a[0]), "r"(a[1]), "r"(a[2]), "r"(a[3]), "r"(b[0]), "r"(b[1]));
}

// ---------------------------------------------------------------------------
// Fused precompute: blocks [0,1024) -> x path; [1024,9216) -> W path
__global__ void precomp_kernel(const float* __restrict__ x,
                               const float* __restrict__ mu,
                               const float* __restrict__ v) {
    __shared__ float mus[256];
    __shared__ float part[8];
    const int t = threadIdx.x, w = t >> 5, l = t & 31;

    if (blockIdx.x < BTOT) {
        int b = blockIdx.x;
        float val = x[b * D_DIM + t];
        g_xhi[b * D_DIM + t] = __float2half_rn(val);
        float s = val * val;
        #pragma unroll
        for (int o = 16; o > 0; o >>= 1) s += __shfl_down_sync(0xffffffffu, s, o);
        if (l == 0) part[w] = s;
        __syncthreads();
        if (t == 0) {
            float tot = 0.f;
            #pragma unroll
            for (int i = 0; i < 8; i++) tot += part[i];
            g_x2[b] = tot;
        }
        return;
    }

    int n = blockIdx.x - BTOT;
    float m = mu[(size_t)n * D_DIM + t];
    mus[t] = m;
    g_whi[(size_t)(n * 9) * D_DIM + t] = __float2half_rn(m);
    float s = m * m;
    #pragma unroll
    for (int o = 16; o > 0; o >>= 1) s += __shfl_down_sync(0xffffffffu, s, o);
    if (l == 0) part[w] = s;
    __syncthreads();
    if (t == 0) {
        float tot = 0.f;
        #pragma unroll
        for (int i = 0; i < 8; i++) tot += part[i];
        g_mu2[n] = tot;
    }
    // warp w handles k = w; lane l covers d = l*8..l*8+7
    const float* vk = v + ((size_t)n * KF + w) * D_DIM + l * 8;
    float4 p0 = *(const float4*)(vk);
    float4 p1 = *(const float4*)(vk + 4);
    float fv[8] = {p0.x, p0.y, p0.z, p0.w, p1.x, p1.y, p1.z, p1.w};
    __half hh[8];
    float hv[8];
    #pragma unroll
    for (int i = 0; i < 8; i++) {
        hh[i] = __float2half_rn(fv[i]);
        hv[i] = __half2float(hh[i]);
    }
    uint4 pk;
    pk.x = (uint32_t)__half_as_ushort(hh[0]) | ((uint32_t)__half_as_ushort(hh[1]) << 16);
    pk.y = (uint32_t)__half_as_ushort(hh[2]) | ((uint32_t)__half_as_ushort(hh[3]) << 16);
    pk.z = (uint32_t)__half_as_ushort(hh[4]) | ((uint32_t)__half_as_ushort(hh[5]) << 16);
    pk.w = (uint32_t)__half_as_ushort(hh[6]) | ((uint32_t)__half_as_ushort(hh[7]) << 16);
    *(uint4*)(g_whi + (size_t)(n * 9 + 1 + w) * D_DIM + l * 8) = pk;
    float dot = 0.f;
    #pragma unroll
    for (int i = 0; i < 8; i++) dot = fmaf(mus[l * 8 + i], hv[i], dot);
    #pragma unroll
    for (int o = 16; o > 0; o >>= 1) dot += __shfl_down_sync(0xffffffffu, dot, o);
    if (l == 0) g_muv[n * KF + w] = dot;
}

// ---------------------------------------------------------------------------
__global__ void __launch_bounds__(NTHREADS, 2)
hmu_mma_kernel(const float* __restrict__ lambda_base,
               const float* __restrict__ omega,
               float* __restrict__ out) {
    extern __shared__ __align__(1024) char smem[];
    const uint32_t sb = smem_u32(smem);
    float* Cs  = (float*)smem;
    float* par = (float*)(smem + PAR_OFF);

    const int t    = threadIdx.x;
    const int wid  = t >> 5;
    const int lane = t & 31;
    const int wm   = wid & 1;       // 2 warps in M (64 rows each)
    const int wn   = wid >> 1;      // 2 warps in N (72 rows each)
    const int bx   = blockIdx.x;
    const int b0   = blockIdx.y * BM;
    const int n0u  = bx * UNITS;

    // cp.async staging: thread covers (row r, 16B seg c), swizzled
    auto load_chunk = [&](int s, int buf) {
        const int d0 = s * KC;
        const uint32_t st = sb + buf * STG;
        // B: 144 rows x 8 segs = 1152
        #pragma unroll
        for (int i = 0; i < 9; i++) {
            int idx = t + NTHREADS * i;
            int r = idx >> 3, c = idx & 7;
            cp16(st + B_O + r * 128 + SWC(c * 16, (r & 7) * 16),
                 g_whi + ((size_t)bx * BN + r) * D_DIM + d0 + c * 8);
        }
        // A: 128 rows x 8 segs = 1024
        #pragma unroll
        for (int i = 0; i < 8; i++) {
            int idx = t + NTHREADS * i;
            int r = idx >> 3, c = idx & 7;
            cp16(st + A_O + r * 128 + SWC(c * 16, (r & 7) * 16),
                 g_xhi + (size_t)(b0 + r) * D_DIM + d0 + c * 8);
        }
    };

    // Prologue: 2 chunks in flight before first compute
    load_chunk(0, 0);
    cp_commit();
    load_chunk(1, 1);
    cp_commit();

    if (t < UNITS) {
        par[t]         = lambda_base[n0u + t];
        par[UNITS + t] = g_mu2[n0u + t];
    }
    par[32 + t]  = g_muv[n0u * KF + t];     // 128 threads = UNITS*KF exactly
    par[160 + t] = omega[n0u * KF + t];

    float acc[4][9][4];
    #pragma unroll
    for (int mi = 0; mi < 4; mi++)
        #pragma unroll
        for (int ni = 0; ni < 9; ni++)
            #pragma unroll
            for (int r = 0; r < 4; r++) acc[mi][ni][r] = 0.f;

    // ldmatrix per-lane address components
    const int mq = lane >> 3, rr = lane & 7;
    const uint32_t rowA  = (uint32_t)(wm * 64 + (mq & 1) * 8 + rr);
    const uint32_t colA  = (uint32_t)((mq >> 1) * 16);
    const uint32_t xorA  = (rowA & 7) * 16;
    const uint32_t rowB  = (uint32_t)(wn * 72 + (mq >> 1) * 8 + rr);
    const uint32_t colB  = (uint32_t)((mq & 1) * 16);
    const uint32_t xorB  = (rowB & 7) * 16;
    const uint32_t rowB2 = (uint32_t)(wn * 72 + 64 + rr);
    const uint32_t colB2 = (uint32_t)(((lane >> 3) & 1) * 16);
    const uint32_t xorB2 = (rowB2 & 7) * 16;

    for (int s = 0; s < NCHUNK; s++) {
        if (s < NCHUNK - 1) cp_wait1(); else cp_wait0();
        __syncthreads();
        if (s < NCHUNK - 2) {
            load_chunk(s + 2, (s + 2) % NSTAGE);
            cp_commit();
        }

        const uint32_t st  = sb + (s % NSTAGE) * STG;
        const uint32_t aB  = st + A_O + rowA * 128;
        const uint32_t bB  = st + B_O + rowB * 128;
        const uint32_t b2B = st + B_O + rowB2 * 128;
        #pragma unroll
        for (int ks = 0; ks < 4; ks++) {       // 4 x k16 per 64-half chunk
            const uint32_t kb = ks * 32;
            uint32_t ah[4][4];
            #pragma unroll
            for (int mi = 0; mi < 4; mi++)
                ldsm4(ah[mi], aB + mi * (16 * 128) + SWC(colA + kb, xorA));
            #pragma unroll
            for (int n2 = 0; n2 < 4; n2++) {
                uint32_t bf[4];
                ldsm4(bf, bB + n2 * (16 * 128) + SWC(colB + kb, xorB));
                #pragma unroll
                for (int mi = 0; mi < 4; mi++) {
                    mma16816(acc[mi][2 * n2],     ah[mi], bf);
                    mma16816(acc[mi][2 * n2 + 1], ah[mi], bf + 2);
                }
            }
            {
                uint32_t bf[2];
                ldsm2(bf, b2B + SWC(colB2 + kb, xorB2));
                #pragma unroll
                for (int mi = 0; mi < 4; mi++)
                    mma16816(acc[mi][8], ah[mi], bf);
            }
        }
    }
    __syncthreads();   // stage-buffer reads done before C-tile overwrite

    // ---- epilogue: regroup 9 columns per unit through smem ----
    const int tg = lane >> 2, tk = lane & 3;
    #pragma unroll
    for (int mi = 0; mi < 4; mi++) {
        #pragma unroll
        for (int rh = 0; rh < 2; rh++) {
            int row = wm * 64 + mi * 16 + tg + rh * 8;
            #pragma unroll
            for (int ni = 0; ni < 9; ni++) {
                int col = wn * 72 + ni * 8 + tk * 2;
                Cs[row * C_STRIDE + col]     = acc[mi][ni][rh * 2];
                Cs[row * C_STRIDE + col + 1] = acc[mi][ni][rh * 2 + 1];
            }
        }
    }
    __syncthreads();

    #pragma unroll
    for (int i = 0; i < 16; i++) {
        int p = t + NTHREADS * i;       // 128 m x 16 u
        int m = p >> 4, u = p & 15;
        const float* c = Cs + m * C_STRIDE + u * 9;
        float xm = c[0];
        float q = par[u] * (g_x2[b0 + m] - 2.f * xm + par[UNITS + u]);
        #pragma unroll
        for (int k = 0; k < KF; k++) {
            float pv = c[1 + k] - par[32 + u * KF + k];
            q = fmaf(par[160 + u * KF + k] * pv, pv, q);
        }
        out[(size_t)(b0 + m) * NTOT + n0u + u] = __expf(q * (-1.0f / 256.0f));
    }
}

// ---------------------------------------------------------------------------
extern "C" void kernel_launch(void* const* d_in, const int* in_sizes, int n_in,
                              void* d_out, int out_size) {
    const float *x = nullptr, *mu = nullptr, *lam = nullptr, *v = nullptr, *om = nullptr;
    for (int i = 0; i < n_in; i++) {
        switch (in_sizes[i]) {
            case BTOT * D_DIM:      x   = (const float*)d_in[i]; break;
            case NTOT * D_DIM:      mu  = (const float*)d_in[i]; break;
            case NTOT:              lam = (const float*)d_in[i]; break;
            case NTOT * KF * D_DIM: v   = (const float*)d_in[i]; break;
            case NTOT * KF:         om  = (const float*)d_in[i]; break;
        }
    }

    precomp_kernel<<<BTOT + NTOT, 256>>>(x, mu, v);

    cudaFuncSetAttribute(hmu_mma_kernel,
                         cudaFuncAttributeMaxDynamicSharedMemorySize, SMEM_TOTAL);
    dim3 grid(NTOT / UNITS, BTOT / BM);   // (512, 8)
    hmu_mma_kernel<<<grid, NTHREADS, SMEM_TOTAL>>>(lam, om, (float*)d_out);
}

// round 13
// speedup vs baseline: 8.2116x; 1.3907x over previous
#include <cuda_runtime.h>
#include <cuda_fp16.h>
#include <cstdint>
#include <cstddef>

// Problem constants
#define D_DIM 256
#define NTOT  8192
#define BTOT  1024
#define KF    8
#define NBX   512                 // n-tiles
#define NT_TILES 4096             // 512 x 8

// GEMM: C(1024 x 73728) = xhi(1024 x 256) @ Whi^T, W rows stored j-major per tile:
// tile row r = j*16 + u_local  (j = 0..8: mu, v0..v7; u_local = 0..15)
#define BM 128
#define BN 144
#define UNITS 16
#define KC 64
#define NCHUNK 4
#define NTHREADS 128

// SMEM: 3-stage ring + double-buffered per-tile params
#define B_O 0
#define A_O (BN*128)                       // 18432
#define STG (A_O + BM*128)                 // 34816
#define NSTAGE 3
#define PAR_OFF (NSTAGE*STG)               // 104448
#define AB_O 0
#define LC_O 1152
#define X2_O 1280
#define PAR_SZ 1792
#define SMEM_TOTAL (PAR_OFF + 2*PAR_SZ)    // 108032

#define SWC(col, xr) ((uint32_t)(col) ^ (uint32_t)(xr))

// Scratch (static __device__, no allocation)
__device__ __align__(16) __half g_xhi[BTOT*D_DIM];
__device__ __align__(16) __half g_whi[(size_t)NTOT*9*D_DIM];   // 37.75 MB, j-major per tile
__device__ __align__(16) float2 g_ab[(size_t)NTOT*9];          // per (tile,u,j): {alpha, beta}
__device__ __align__(16) float2 g_lc[NTOT];                    // {lambda, C}
__device__ __align__(16) float  g_x2[BTOT];

// ---------------------------------------------------------------------------
__device__ __forceinline__ uint32_t smem_u32(const void* p) {
    uint32_t a;
    asm("{ .reg .u64 t; cvta.to.shared.u64 t, %1; cvt.u32.u64 %0, t; }"
        : "=r"(a) : "l"(p));
    return a;
}
__device__ __forceinline__ void cp16(uint32_t dst, const void* src) {
    asm volatile("cp.async.cg.shared.global [%0], [%1], 16;" :: "r"(dst), "l"(src));
}
__device__ __forceinline__ void cp_commit() {
    asm volatile("cp.async.commit_group;" ::: "memory");
}
__device__ __forceinline__ void cp_wait1() {
    asm volatile("cp.async.wait_group 1;" ::: "memory");
}
__device__ __forceinline__ void ldsm4(uint32_t* d, uint32_t a) {
    asm volatile("ldmatrix.sync.aligned.m8n8.x4.shared.b16 {%0,%1,%2,%3}, [%4];"
        : "=r"(d[0]), "=r"(d[1]), "=r"(d[2]), "=r"(d[3]) : "r"(a));
}
__device__ __forceinline__ void ldsm2(uint32_t* d, uint32_t a) {
    asm volatile("ldmatrix.sync.aligned.m8n8.x2.shared.b16 {%0,%1}, [%2];"
        : "=r"(d[0]), "=r"(d[1]) : "r"(a));
}
__device__ __forceinline__ void mma16816(float* c, const uint32_t* a, const uint32_t* b) {
    asm volatile(
        "mma.sync.aligned.m16n8k16.row.col.f32.f16.f16.f32 "
        "{%0,%1,%2,%3}, {%4,%5,%6,%7}, {%8,%9}, {%0,%1,%2,%3};"
        : "+f"(c[0]), "+f"(c[1]), "+f"(c[2]), "+f"(c[3])
        : "r"(a[0]), "r"(a[1]), "r"(a[2]), "r"(a[3]), "r"(b[0]), "r"(b[1]));
}

// ---------------------------------------------------------------------------
// Fused precompute: blocks [0,1024) -> x path; [1024,9216) -> W path
__global__ void precomp_kernel(const float* __restrict__ x,
                               const float* __restrict__ mu,
                               const float* __restrict__ v,
                               const float* __restrict__ lambda_base,
                               const float* __restrict__ omega) {
    __shared__ float mus[256];
    __shared__ float part[8];
    __shared__ float muvs[8];
    __shared__ float mu2s;
    const int t = threadIdx.x, w = t >> 5, l = t & 31;

    if (blockIdx.x < BTOT) {
        int b = blockIdx.x;
        float val = x[b * D_DIM + t];
        g_xhi[b * D_DIM + t] = __float2half_rn(val);
        float s = val * val;
        #pragma unroll
        for (int o = 16; o > 0; o >>= 1) s += __shfl_down_sync(0xffffffffu, s, o);
        if (l == 0) part[w] = s;
        __syncthreads();
        if (t == 0) {
            float tot = 0.f;
            #pragma unroll
            for (int i = 0; i < 8; i++) tot += part[i];
            g_x2[b] = tot;
        }
        return;
    }

    const int n = blockIdx.x - BTOT;
    const int bxw = n >> 4, ul = n & 15;
    float m = mu[(size_t)n * D_DIM + t];
    mus[t] = m;
    // mu row -> j=0 block
    g_whi[((size_t)bxw * 144 + ul) * D_DIM + t] = __float2half_rn(m);
    float s = m * m;
    #pragma unroll
    for (int o = 16; o > 0; o >>= 1) s += __shfl_down_sync(0xffffffffu, s, o);
    if (l == 0) part[w] = s;
    __syncthreads();
    if (t == 0) {
        float tot = 0.f;
        #pragma unroll
        for (int i = 0; i < 8; i++) tot += part[i];
        mu2s = tot;
    }
    // warp w handles k = w; lane l covers d = l*8..l*8+7
    const float* vk = v + ((size_t)n * KF + w) * D_DIM + l * 8;
    float4 p0 = *(const float4*)(vk);
    float4 p1 = *(const float4*)(vk + 4);
    float fv[8] = {p0.x, p0.y, p0.z, p0.w, p1.x, p1.y, p1.z, p1.w};
    __half hh[8];
    float hv[8];
    #pragma unroll
    for (int i = 0; i < 8; i++) {
        hh[i] = __float2half_rn(fv[i]);
        hv[i] = __half2float(hh[i]);
    }
    uint4 pk;
    pk.x = (uint32_t)__half_as_ushort(hh[0]) | ((uint32_t)__half_as_ushort(hh[1]) << 16);
    pk.y = (uint32_t)__half_as_ushort(hh[2]) | ((uint32_t)__half_as_ushort(hh[3]) << 16);
    pk.z = (uint32_t)__half_as_ushort(hh[4]) | ((uint32_t)__half_as_ushort(hh[5]) << 16);
    pk.w = (uint32_t)__half_as_ushort(hh[6]) | ((uint32_t)__half_as_ushort(hh[7]) << 16);
    // v_k row -> j=k+1 block
    *(uint4*)(g_whi + ((size_t)bxw * 144 + (w + 1) * 16 + ul) * D_DIM + l * 8) = pk;
    float dot = 0.f;
    #pragma unroll
    for (int i = 0; i < 8; i++) dot = fmaf(mus[l * 8 + i], hv[i], dot);
    #pragma unroll
    for (int o = 16; o > 0; o >>= 1) dot += __shfl_down_sync(0xffffffffu, dot, o);
    if (l == 0) muvs[w] = dot;
    __syncthreads();

    if (t < 9) {
        float lam = lambda_base[n];
        float2 ab;
        if (t == 0) {
            ab.x = 0.f;
            ab.y = -2.f * lam;
        } else {
            float om = omega[n * KF + t - 1];
            ab.x = om;
            ab.y = -2.f * om * muvs[t - 1];
        }
        g_ab[(size_t)bxw * 144 + ul * 9 + t] = ab;
    }
    if (t == 0) {
        float lam = lambda_base[n];
        float C = lam * mu2s;
        #pragma unroll
        for (int k = 0; k < KF; k++) {
            float om = omega[n * KF + k];
            C = fmaf(om * muvs[k], muvs[k], C);
        }
        float2 lc;
        lc.x = lam;
        lc.y = C;
        g_lc[n] = lc;
    }
}

// ---------------------------------------------------------------------------
__global__ void __launch_bounds__(NTHREADS, 2)
hmu_mma_kernel(float* __restrict__ out) {
    extern __shared__ __align__(1024) char smem[];
    const uint32_t sb = smem_u32(smem);

    const int t    = threadIdx.x;
    const int wid  = t >> 5;
    const int lane = t & 31;
    const int wm   = wid & 1;       // 2 warps in M (64 rows each)
    const int wn   = wid >> 1;      // 2 warps in N (8 units each)
    const int tg   = lane >> 2, tk = lane & 3;
    const int nCTA = gridDim.x;

    // ldmatrix lane addressing (row%8 == rr for all tiles -> common xor)
    const int mq = lane >> 3, rr = lane & 7;
    const uint32_t xorR = (uint32_t)rr * 16;
    const uint32_t rowA  = (uint32_t)(wm * 64 + (mq & 1) * 8 + rr);
    const uint32_t colA  = (uint32_t)((mq >> 1) * 16);
    const uint32_t rowBb = (uint32_t)(16 * (mq >> 1) + 8 * wn + rr);  // + 32*n2
    const uint32_t colB  = (uint32_t)((mq & 1) * 16);
    const uint32_t rowB2 = (uint32_t)(128 + 8 * wn + rr);
    const uint32_t colB2 = (uint32_t)(((lane >> 3) & 1) * 16);

    // pp < 0: no param prefetch; else param buffer index
    auto load_chunk = [&](int bx, int by, int s, int buf, int pp) {
        const int d0 = s * KC;
        const uint32_t st = sb + buf * STG;
        #pragma unroll
        for (int i = 0; i < 9; i++) {
            int idx = t + NTHREADS * i;
            int r = idx >> 3, c = idx & 7;
            cp16(st + B_O + r * 128 + SWC(c * 16, (r & 7) * 16),
                 g_whi + ((size_t)bx * BN + r) * D_DIM + d0 + c * 8);
        }
        #pragma unroll
        for (int i = 0; i < 8; i++) {
            int idx = t + NTHREADS * i;
            int r = idx >> 3, c = idx & 7;
            cp16(st + A_O + r * 128 + SWC(c * 16, (r & 7) * 16),
                 g_xhi + (size_t)(by * BM + r) * D_DIM + d0 + c * 8);
        }
        if (pp >= 0) {
            uint32_t pb = sb + PAR_OFF + (uint32_t)pp * PAR_SZ;
            if (t < 72)
                cp16(pb + AB_O + t * 16, (const char*)(g_ab + (size_t)bx * 144) + t * 16);
            else if (t < 80)
                cp16(pb + LC_O + (t - 72) * 16, (const char*)(g_lc + bx * 16) + (t - 72) * 16);
            else if (t < 112)
                cp16(pb + X2_O + (t - 80) * 16, (const char*)(g_x2 + by * BM) + (t - 80) * 16);
        }
    };

    // Prologue: first tile's chunks 0,1 (+ its params)
    {
        const int t0 = blockIdx.x;
        load_chunk(t0 & (NBX - 1), t0 >> 9, 0, 0, 0);
        cp_commit();
        load_chunk(t0 & (NBX - 1), t0 >> 9, 1, 1, -1);
        cp_commit();
    }

    float acc[4][9][4];
    int g = 0, tp = 0;

    for (int tile = blockIdx.x; tile < NT_TILES; tile += nCTA, tp ^= 1) {
        const int bx = tile & (NBX - 1), by = tile >> 9;

        #pragma unroll
        for (int mi = 0; mi < 4; mi++)
            #pragma unroll
            for (int ni = 0; ni < 9; ni++)
                #pragma unroll
                for (int r = 0; r < 4; r++) acc[mi][ni][r] = 0.f;

        for (int s = 0; s < NCHUNK; s++) {
            cp_wait1();
            __syncthreads();
            {   // issue load for virtual chunk g+2 (may belong to next tile)
                int s2 = s + 2, t2 = tile;
                if (s2 >= NCHUNK) { s2 -= NCHUNK; t2 += nCTA; }
                if (t2 < NT_TILES)
                    load_chunk(t2 & (NBX - 1), t2 >> 9, s2, (g + 2) % NSTAGE,
                               (s2 == 0) ? (tp ^ 1) : -1);
                cp_commit();
            }
            const uint32_t st = sb + (g % NSTAGE) * STG;
            #pragma unroll
            for (int ks = 0; ks < 4; ks++) {
                const uint32_t kb = ks * 32;
                uint32_t ah[4][4];
                #pragma unroll
                for (int mi = 0; mi < 4; mi++)
                    ldsm4(ah[mi], st + A_O + (rowA + mi * 16) * 128 + SWC(colA + kb, xorR));
                #pragma unroll
                for (int n2 = 0; n2 < 4; n2++) {
                    uint32_t bf[4];
                    ldsm4(bf, st + B_O + (rowBb + 32 * n2) * 128 + SWC(colB + kb, xorR));
                    #pragma unroll
                    for (int mi = 0; mi < 4; mi++) {
                        mma16816(acc[mi][2 * n2],     ah[mi], bf);
                        mma16816(acc[mi][2 * n2 + 1], ah[mi], bf + 2);
                    }
                }
                {
                    uint32_t bf2[2];
                    ldsm2(bf2, st + B_O + rowB2 * 128 + SWC(colB2 + kb, xorR));
                    #pragma unroll
                    for (int mi = 0; mi < 4; mi++)
                        mma16816(acc[mi][8], ah[mi], bf2);
                }
            }
            g++;
        }

        // ---- register epilogue: lane owns units ua, ua+1 across all 9 j ----
        {
            const char* parb = smem + PAR_OFF + tp * PAR_SZ;
            const float2* abp = (const float2*)(parb + AB_O);
            const float2* lcp = (const float2*)(parb + LC_O);
            const float*  x2p = (const float*)(parb + X2_O);
            const int ua = 8 * wn + 2 * tk;
            float2 A0[9], A1[9];
            #pragma unroll
            for (int j = 0; j < 9; j++) {
                A0[j] = abp[ua * 9 + j];
                A1[j] = abp[ua * 9 + 9 + j];
            }
            const float2 lca = lcp[ua], lcb = lcp[ua + 1];
            float* ob = out + (size_t)(by * BM) * NTOT + bx * UNITS + ua;
            #pragma unroll
            for (int mi = 0; mi < 4; mi++)
                #pragma unroll
                for (int rh = 0; rh < 2; rh++) {
                    const int row = wm * 64 + mi * 16 + tg + rh * 8;
                    const float x2r = x2p[row];
                    float qa = fmaf(lca.x, x2r, lca.y);
                    float qb = fmaf(lcb.x, x2r, lcb.y);
                    #pragma unroll
                    for (int j = 0; j < 9; j++) {
                        float da = acc[mi][j][rh * 2 + 0];
                        float db = acc[mi][j][rh * 2 + 1];
                        qa = fmaf(da, fmaf(A0[j].x, da, A0[j].y), qa);
                        qb = fmaf(db, fmaf(A1[j].x, db, A1[j].y), qb);
                    }
                    float2 o;
                    o.x = __expf(qa * (-1.0f / 256.0f));
                    o.y = __expf(qb * (-1.0f / 256.0f));
                    *(float2*)(ob + (size_t)row * NTOT) = o;
                }
        }
    }
}

// ---------------------------------------------------------------------------
extern "C" void kernel_launch(void* const* d_in, const int* in_sizes, int n_in,
                              void* d_out, int out_size) {
    const float *x = nullptr, *mu = nullptr, *lam = nullptr, *v = nullptr, *om = nullptr;
    for (int i = 0; i < n_in; i++) {
        switch (in_sizes[i]) {
            case BTOT * D_DIM:      x   = (const float*)d_in[i]; break;
            case NTOT * D_DIM:      mu  = (const float*)d_in[i]; break;
            case NTOT:              lam = (const float*)d_in[i]; break;
            case NTOT * KF * D_DIM: v   = (const float*)d_in[i]; break;
            case NTOT * KF:         om  = (const float*)d_in[i]; break;
        }
    }

    precomp_kernel<<<BTOT + NTOT, 256>>>(x, mu, v, lam, om);

    int nsm = 0;
    cudaDeviceGetAttribute(&nsm, cudaDevAttrMultiProcessorCount, 0);
    if (nsm <= 0) nsm = 148;
    int grid = 2 * nsm;
    if (grid > NT_TILES) grid = NT_TILES;

    cudaFuncSetAttribute(hmu_mma_kernel,
                         cudaFuncAttributeMaxDynamicSharedMemorySize, SMEM_TOTAL);
    hmu_mma_kernel<<<grid, NTHREADS, SMEM_TOTAL>>>((float*)d_out);
}

// round 14
// speedup vs baseline: 8.2354x; 1.0029x over previous
#include <cuda_runtime.h>
#include <cuda_fp16.h>
#include <cstdint>
#include <cstddef>

// Problem constants
#define D_DIM 256
#define NTOT  8192
#define BTOT  1024
#define KF    8
#define NBX   512                 // n-tiles per band
#define NBANDS 8                  // b-bands (by)

// GEMM: C(1024 x 73728) = xhi(1024 x 256) @ Whi^T, W rows j-major per tile:
// tile row r = j*16 + u_local
#define BM 128
#define BN 144
#define UNITS 16
#define KC 64
#define NCHUNK 4
#define NTHREADS 128

// SMEM: resident A (all K) + 2-stage B ring + params
#define A_RES 0                          // 4 blocks of 16384 (one per 64-half chunk)
#define B_O   65536
#define BSTG  18432                      // 144 rows * 128B
#define PAR_OFF (B_O + 2*BSTG)           // 102400
#define X2_O  PAR_OFF                    // 512B, band-constant
#define ABLC_O (PAR_OFF + 512)           // 2 buffers * 1280B (ab 1152 + lc 128)
#define SMEM_TOTAL (ABLC_O + 2*1280)     // 105472

#define SWC(col, xr) ((uint32_t)(col) ^ (uint32_t)(xr))

// Scratch (static __device__, no allocation)
__device__ __align__(16) __half g_xhi[BTOT*D_DIM];
__device__ __align__(16) __half g_whi[(size_t)NTOT*9*D_DIM];   // 37.75 MB, j-major per tile
__device__ __align__(16) float2 g_ab[(size_t)NTOT*9];          // per (tile,u,j): {alpha, beta}
__device__ __align__(16) float2 g_lc[NTOT];                    // {lambda, C}
__device__ __align__(16) float  g_x2[BTOT];

// ---------------------------------------------------------------------------
__device__ __forceinline__ uint32_t smem_u32(const void* p) {
    uint32_t a;
    asm("{ .reg .u64 t; cvta.to.shared.u64 t, %1; cvt.u32.u64 %0, t; }"
        : "=r"(a) : "l"(p));
    return a;
}
__device__ __forceinline__ void cp16(uint32_t dst, const void* src) {
    asm volatile("cp.async.cg.shared.global [%0], [%1], 16;" :: "r"(dst), "l"(src));
}
__device__ __forceinline__ void cp_commit() {
    asm volatile("cp.async.commit_group;" ::: "memory");
}
__device__ __forceinline__ void cp_wait0() {
    asm volatile("cp.async.wait_group 0;" ::: "memory");
}
__device__ __forceinline__ void ldsm4(uint32_t* d, uint32_t a) {
    asm volatile("ldmatrix.sync.aligned.m8n8.x4.shared.b16 {%0,%1,%2,%3}, [%4];"
        : "=r"(d[0]), "=r"(d[1]), "=r"(d[2]), "=r"(d[3]) : "r"(a));
}
__device__ __forceinline__ void ldsm2(uint32_t* d, uint32_t a) {
    asm volatile("ldmatrix.sync.aligned.m8n8.x2.shared.b16 {%0,%1}, [%2];"
        : "=r"(d[0]), "=r"(d[1]) : "r"(a));
}
__device__ __forceinline__ void mma16816(float* c, const uint32_t* a, const uint32_t* b) {
    asm volatile(
        "mma.sync.aligned.m16n8k16.row.col.f32.f16.f16.f32 "
        "{%0,%1,%2,%3}, {%4,%5,%6,%7}, {%8,%9}, {%0,%1,%2,%3};"
        : "+f"(c[0]), "+f"(c[1]), "+f"(c[2]), "+f"(c[3])
        : "r"(a[0]), "r"(a[1]), "r"(a[2]), "r"(a[3]), "r"(b[0]), "r"(b[1]));
}

// ---------------------------------------------------------------------------
// Fused precompute: blocks [0,1024) -> x path; [1024,9216) -> W path
__global__ void precomp_kernel(const float* __restrict__ x,
                               const float* __restrict__ mu,
                               const float* __restrict__ v,
                               const float* __restrict__ lambda_base,
                               const float* __restrict__ omega) {
    __shared__ float mus[256];
    __shared__ float part[8];
    __shared__ float muvs[8];
    __shared__ float mu2s;
    const int t = threadIdx.x, w = t >> 5, l = t & 31;

    if (blockIdx.x < BTOT) {
        int b = blockIdx.x;
        float val = x[b * D_DIM + t];
        g_xhi[b * D_DIM + t] = __float2half_rn(val);
        float s = val * val;
        #pragma unroll
        for (int o = 16; o > 0; o >>= 1) s += __shfl_down_sync(0xffffffffu, s, o);
        if (l == 0) part[w] = s;
        __syncthreads();
        if (t == 0) {
            float tot = 0.f;
            #pragma unroll
            for (int i = 0; i < 8; i++) tot += part[i];
            g_x2[b] = tot;
        }
        return;
    }

    const int n = blockIdx.x - BTOT;
    const int bxw = n >> 4, ul = n & 15;
    float m = mu[(size_t)n * D_DIM + t];
    mus[t] = m;
    g_whi[((size_t)bxw * 144 + ul) * D_DIM + t] = __float2half_rn(m);
    float s = m * m;
    #pragma unroll
    for (int o = 16; o > 0; o >>= 1) s += __shfl_down_sync(0xffffffffu, s, o);
    if (l == 0) part[w] = s;
    __syncthreads();
    if (t == 0) {
        float tot = 0.f;
        #pragma unroll
        for (int i = 0; i < 8; i++) tot += part[i];
        mu2s = tot;
    }
    const float* vk = v + ((size_t)n * KF + w) * D_DIM + l * 8;
    float4 p0 = *(const float4*)(vk);
    float4 p1 = *(const float4*)(vk + 4);
    float fv[8] = {p0.x, p0.y, p0.z, p0.w, p1.x, p1.y, p1.z, p1.w};
    __half hh[8];
    float hv[8];
    #pragma unroll
    for (int i = 0; i < 8; i++) {
        hh[i] = __float2half_rn(fv[i]);
        hv[i] = __half2float(hh[i]);
    }
    uint4 pk;
    pk.x = (uint32_t)__half_as_ushort(hh[0]) | ((uint32_t)__half_as_ushort(hh[1]) << 16);
    pk.y = (uint32_t)__half_as_ushort(hh[2]) | ((uint32_t)__half_as_ushort(hh[3]) << 16);
    pk.z = (uint32_t)__half_as_ushort(hh[4]) | ((uint32_t)__half_as_ushort(hh[5]) << 16);
    pk.w = (uint32_t)__half_as_ushort(hh[6]) | ((uint32_t)__half_as_ushort(hh[7]) << 16);
    *(uint4*)(g_whi + ((size_t)bxw * 144 + (w + 1) * 16 + ul) * D_DIM + l * 8) = pk;
    float dot = 0.f;
    #pragma unroll
    for (int i = 0; i < 8; i++) dot = fmaf(mus[l * 8 + i], hv[i], dot);
    #pragma unroll
    for (int o = 16; o > 0; o >>= 1) dot += __shfl_down_sync(0xffffffffu, dot, o);
    if (l == 0) muvs[w] = dot;
    __syncthreads();

    if (t < 9) {
        float lam = lambda_base[n];
        float2 ab;
        if (t == 0) {
            ab.x = 0.f;
            ab.y = -2.f * lam;
        } else {
            float om = omega[n * KF + t - 1];
            ab.x = om;
            ab.y = -2.f * om * muvs[t - 1];
        }
        g_ab[(size_t)bxw * 144 + ul * 9 + t] = ab;
    }
    if (t == 0) {
        float lam = lambda_base[n];
        float C = lam * mu2s;
        #pragma unroll
        for (int k = 0; k < KF; k++) {
            float om = omega[n * KF + k];
            C = fmaf(om * muvs[k], muvs[k], C);
        }
        float2 lc;
        lc.x = lam;
        lc.y = C;
        g_lc[n] = lc;
    }
}

// ---------------------------------------------------------------------------
__global__ void __launch_bounds__(NTHREADS, 2)
hmu_mma_kernel(float* __restrict__ out) {
    extern __shared__ __align__(1024) char smem[];
    const uint32_t sb = smem_u32(smem);

    const int t    = threadIdx.x;
    const int wid  = t >> 5;
    const int lane = t & 31;
    const int wm   = wid & 1;       // 2 warps in M (64 rows each)
    const int wn   = wid >> 1;      // 2 warps in N (8 units each)
    const int tg   = lane >> 2, tk = lane & 3;

    const int per_band = gridDim.x >> 3;            // CTAs per by-band
    const int band = blockIdx.x / per_band;         // = by
    const int idx0 = blockIdx.x - band * per_band;
    const int by   = band;

    // ldmatrix lane addressing
    const int mq = lane >> 3, rr = lane & 7;
    const uint32_t xorR  = (uint32_t)rr * 16;
    const uint32_t rowA  = (uint32_t)(wm * 64 + (mq & 1) * 8 + rr);
    const uint32_t colA  = (uint32_t)((mq >> 1) * 16);
    const uint32_t rowBb = (uint32_t)(16 * (mq >> 1) + 8 * wn + rr);  // + 32*n2
    const uint32_t colB  = (uint32_t)((mq & 1) * 16);
    const uint32_t rowB2 = (uint32_t)(128 + 8 * wn + rr);
    const uint32_t colB2 = (uint32_t)(((lane >> 3) & 1) * 16);

    // B chunk loader; pp>=0 also prefetches next tile's (ab,lc) into buffer pp
    auto load_B = [&](int bx, int s, int buf, int pp) {
        const int d0 = s * KC;
        const uint32_t stB = sb + B_O + (uint32_t)buf * BSTG;
        #pragma unroll
        for (int i = 0; i < 9; i++) {
            int idx = t + NTHREADS * i;
            int r = idx >> 3, c = idx & 7;
            cp16(stB + r * 128 + SWC(c * 16, (r & 7) * 16),
                 g_whi + ((size_t)bx * BN + r) * D_DIM + d0 + c * 8);
        }
        if (pp >= 0) {
            uint32_t pb = sb + ABLC_O + (uint32_t)pp * 1280;
            if (t < 72)
                cp16(pb + t * 16, (const char*)(g_ab + (size_t)bx * 144) + t * 16);
            else if (t < 80)
                cp16(pb + 1152 + (t - 72) * 16, (const char*)(g_lc + bx * 16) + (t - 72) * 16);
        }
    };

    // ---- prologue: resident A (all 4 chunks), band x2, first B chunk + params ----
    #pragma unroll
    for (int c = 0; c < 4; c++) {
        #pragma unroll
        for (int i = 0; i < 8; i++) {
            int idx = t + NTHREADS * i;
            int r = idx >> 3, cc = idx & 7;
            cp16(sb + A_RES + c * 16384 + r * 128 + SWC(cc * 16, (r & 7) * 16),
                 g_xhi + (size_t)(by * BM + r) * D_DIM + c * KC + cc * 8);
        }
    }
    if (t < 32) cp16(sb + X2_O + t * 16, (const char*)(g_x2 + by * BM) + t * 16);
    load_B(idx0, 0, 0, 0);
    cp_commit();

    float acc[4][9][4];
    int tp = 0;

    for (int bx = idx0; bx < NBX; bx += per_band, tp ^= 1) {
        #pragma unroll
        for (int mi = 0; mi < 4; mi++)
            #pragma unroll
            for (int ni = 0; ni < 9; ni++)
                #pragma unroll
                for (int r = 0; r < 4; r++) acc[mi][ni][r] = 0.f;

        for (int s = 0; s < NCHUNK; s++) {
            cp_wait0();
            __syncthreads();
            {   // issue next B chunk (may roll into next tile, carrying params)
                int s2 = s + 1, bx2 = bx, pp = -1;
                if (s2 == NCHUNK) { s2 = 0; bx2 = bx + per_band; pp = tp ^ 1; }
                if (bx2 < NBX) load_B(bx2, s2, (s + 1) & 1, pp);
                cp_commit();
            }
            const uint32_t stA = sb + A_RES + (uint32_t)s * 16384;
            const uint32_t stB = sb + B_O + (uint32_t)(s & 1) * BSTG;
            #pragma unroll
            for (int ks = 0; ks < 4; ks++) {
                const uint32_t kb = ks * 32;
                uint32_t ah[4][4];
                #pragma unroll
                for (int mi = 0; mi < 4; mi++)
                    ldsm4(ah[mi], stA + (rowA + mi * 16) * 128 + SWC(colA + kb, xorR));
                #pragma unroll
                for (int n2 = 0; n2 < 4; n2++) {
                    uint32_t bf[4];
                    ldsm4(bf, stB + (rowBb + 32 * n2) * 128 + SWC(colB + kb, xorR));
                    #pragma unroll
                    for (int mi = 0; mi < 4; mi++) {
                        mma16816(acc[mi][2 * n2],     ah[mi], bf);
                        mma16816(acc[mi][2 * n2 + 1], ah[mi], bf + 2);
                    }
                }
                {
                    uint32_t bf2[2];
                    ldsm2(bf2, stB + rowB2 * 128 + SWC(colB2 + kb, xorR));
                    #pragma unroll
                    for (int mi = 0; mi < 4; mi++)
                        mma16816(acc[mi][8], ah[mi], bf2);
                }
            }
        }

        // ---- register epilogue: lane owns units ua, ua+1 across all 9 j ----
        {
            const char* pb = smem + ABLC_O + tp * 1280;
            const float2* abp = (const float2*)pb;
            const float2* lcp = (const float2*)(pb + 1152);
            const float*  x2p = (const float*)(smem + X2_O);
            const int ua = 8 * wn + 2 * tk;
            float2 A0[9], A1[9];
            #pragma unroll
            for (int j = 0; j < 9; j++) {
                A0[j] = abp[ua * 9 + j];
                A1[j] = abp[ua * 9 + 9 + j];
            }
            const float2 lca = lcp[ua], lcb = lcp[ua + 1];
            float* ob = out + (size_t)(by * BM) * NTOT + bx * UNITS + ua;
            #pragma unroll
            for (int mi = 0; mi < 4; mi++)
                #pragma unroll
                for (int rh = 0; rh < 2; rh++) {
                    const int row = wm * 64 + mi * 16 + tg + rh * 8;
                    const float x2r = x2p[row];
                    float qa = fmaf(lca.x, x2r, lca.y);
                    float qb = fmaf(lcb.x, x2r, lcb.y);
                    #pragma unroll
                    for (int j = 0; j < 9; j++) {
                        float da = acc[mi][j][rh * 2 + 0];
                        float db = acc[mi][j][rh * 2 + 1];
                        qa = fmaf(da, fmaf(A0[j].x, da, A0[j].y), qa);
                        qb = fmaf(db, fmaf(A1[j].x, db, A1[j].y), qb);
                    }
                    float2 o;
                    o.x = __expf(qa * (-1.0f / 256.0f));
                    o.y = __expf(qb * (-1.0f / 256.0f));
                    *(float2*)(ob + (size_t)row * NTOT) = o;
                }
        }
    }
}

// ---------------------------------------------------------------------------
extern "C" void kernel_launch(void* const* d_in, const int* in_sizes, int n_in,
                              void* d_out, int out_size) {
    const float *x = nullptr, *mu = nullptr, *lam = nullptr, *v = nullptr, *om = nullptr;
    for (int i = 0; i < n_in; i++) {
        switch (in_sizes[i]) {
            case BTOT * D_DIM:      x   = (const float*)d_in[i]; break;
            case NTOT * D_DIM:      mu  = (const float*)d_in[i]; break;
            case NTOT:              lam = (const float*)d_in[i]; break;
            case NTOT * KF * D_DIM: v   = (const float*)d_in[i]; break;
            case NTOT * KF:         om  = (const float*)d_in[i]; break;
        }
    }

    precomp_kernel<<<BTOT + NTOT, 256>>>(x, mu, v, lam, om);

    int nsm = 0;
    cudaDeviceGetAttribute(&nsm, cudaDevAttrMultiProcessorCount, 0);
    if (nsm <= 0) nsm = 148;
    int per_band = (2 * nsm) / NBANDS;          // 38 on 152-SM GB300
    if (per_band < 1) per_band = 1;
    int grid = NBANDS * per_band;

    cudaFuncSetAttribute(hmu_mma_kernel,
                         cudaFuncAttributeMaxDynamicSharedMemorySize, SMEM_TOTAL);
    hmu_mma_kernel<<<grid, NTHREADS, SMEM_TOTAL>>>((float*)d_out);
}